// round 1
// baseline (speedup 1.0000x reference)
#include <cuda_runtime.h>
#include <math.h>

// ---------------------------------------------------------------------------
// GraphSAGE fraud detector, fp32 baseline.
// N<=50048 nodes, F=128, H=512. Scratch in __device__ globals (no allocs).
// ---------------------------------------------------------------------------

#define MAXN 50048
#define HDIM 512
#define FDIM 128

__device__ float g_deg[MAXN];                         // degree, then 1/max(deg,1)
__device__ float g_agg[(size_t)MAXN * HDIM];          // reused for both layers
__device__ float g_h1 [(size_t)MAXN * HDIM];
__device__ float g_h2 [(size_t)MAXN * HDIM];

// ---------------- utility kernels ----------------

__global__ void zero1_kernel(float* __restrict__ p, int n) {
    int i = blockIdx.x * blockDim.x + threadIdx.x;
    if (i < n) p[i] = 0.0f;
}

__global__ void zero4_kernel(float4* __restrict__ p, int n4) {
    int i = blockIdx.x * blockDim.x + threadIdx.x;
    if (i < n4) p[i] = make_float4(0.f, 0.f, 0.f, 0.f);
}

__global__ void deg_kernel(const int* __restrict__ dst, int E, float* __restrict__ deg) {
    int e = blockIdx.x * blockDim.x + threadIdx.x;
    if (e < E) atomicAdd(&deg[dst[e]], 1.0f);
}

__global__ void invdeg_kernel(float* __restrict__ deg, int n) {
    int i = blockIdx.x * blockDim.x + threadIdx.x;
    if (i < n) deg[i] = 1.0f / fmaxf(deg[i], 1.0f);
}

// ---------------- edge scatter: agg[dst] += feat[src] ----------------
// One thread per (edge, float4 column). All 32 lanes of a warp share an edge
// when D4 >= 32, so index loads broadcast and the float4 gather is coalesced.
__global__ void scatter_kernel(const float* __restrict__ feat,
                               const int* __restrict__ src,
                               const int* __restrict__ dst,
                               float* __restrict__ outbuf,
                               long long total, int log2d4) {
    long long t = (long long)blockIdx.x * blockDim.x + threadIdx.x;
    if (t >= total) return;
    int d4mask = (1 << log2d4) - 1;
    int e = (int)(t >> log2d4);
    int c = (int)t & d4mask;
    int s = src[e];
    int d = dst[e];
    int D4 = 1 << log2d4;
    float4 v = ((const float4*)feat)[(long long)s * D4 + c];
    float* o = outbuf + (((long long)d * D4 + c) << 2);
    atomicAdd(o + 0, v.x);
    atomicAdd(o + 1, v.y);
    atomicAdd(o + 2, v.z);
    atomicAdd(o + 3, v.w);
}

// ---------------- fused concat-GEMM + bias + ReLU ----------------
// C[m, n] = relu( sum_k concat(A1[m,:], A2[m,:]*invd[m])[k] * W[n, k] + bias[n] )
// A1, A2: [M, Kh] row-major.  W: [512, 2*Kh] row-major.  C: [M, 512].
// Block tile 128x128, BK=16, per-thread 8x8, 256 threads.
__global__ void __launch_bounds__(256, 2)
gemm_cat_relu(const float* __restrict__ A1,
              const float* __restrict__ A2,
              const float* __restrict__ invd,
              const float* __restrict__ W,
              const float* __restrict__ bias,
              float* __restrict__ C,
              int M, int Kh) {
    const int BK = 16;
    __shared__ float As[BK][128];
    __shared__ float Bs[BK][128];

    const int bm = blockIdx.x * 128;
    const int bn = blockIdx.y * 128;
    const int tid = threadIdx.x;
    const int tx = tid & 15;      // 0..15 -> n
    const int ty = tid >> 4;      // 0..15 -> m
    const int K = 2 * Kh;

    // loader mapping: rows r = tid>>2 (0..63) and r+64; k quad = (tid&3)*4
    const int lr = tid >> 2;
    const int lk = (tid & 3) << 2;

    float acc[8][8];
#pragma unroll
    for (int i = 0; i < 8; ++i)
#pragma unroll
        for (int j = 0; j < 8; ++j) acc[i][j] = 0.0f;

    for (int k0 = 0; k0 < K; k0 += BK) {
        // ---- load A tile (with concat + invdeg scaling) ----
#pragma unroll
        for (int h = 0; h < 2; ++h) {
            int m  = bm + lr + h * 64;
            int kg = k0 + lk;
            float4 v = make_float4(0.f, 0.f, 0.f, 0.f);
            if (m < M) {
                if (kg < Kh) {
                    v = *(const float4*)(A1 + (long long)m * Kh + kg);
                } else {
                    v = *(const float4*)(A2 + (long long)m * Kh + (kg - Kh));
                    float s = invd[m];
                    v.x *= s; v.y *= s; v.z *= s; v.w *= s;
                }
            }
            As[lk + 0][lr + h * 64] = v.x;
            As[lk + 1][lr + h * 64] = v.y;
            As[lk + 2][lr + h * 64] = v.z;
            As[lk + 3][lr + h * 64] = v.w;
        }
        // ---- load B tile (W rows) ----
#pragma unroll
        for (int h = 0; h < 2; ++h) {
            int n  = bn + lr + h * 64;
            int kg = k0 + lk;
            float4 v = *(const float4*)(W + (long long)n * K + kg);
            Bs[lk + 0][lr + h * 64] = v.x;
            Bs[lk + 1][lr + h * 64] = v.y;
            Bs[lk + 2][lr + h * 64] = v.z;
            Bs[lk + 3][lr + h * 64] = v.w;
        }
        __syncthreads();

#pragma unroll
        for (int kk = 0; kk < BK; ++kk) {
            float a[8], b[8];
#pragma unroll
            for (int i = 0; i < 8; ++i) a[i] = As[kk][ty * 8 + i];
#pragma unroll
            for (int j = 0; j < 8; ++j) b[j] = Bs[kk][tx * 8 + j];
#pragma unroll
            for (int i = 0; i < 8; ++i)
#pragma unroll
                for (int j = 0; j < 8; ++j) acc[i][j] += a[i] * b[j];
        }
        __syncthreads();
    }

    // ---- epilogue: bias + ReLU, vectorized store ----
#pragma unroll
    for (int i = 0; i < 8; ++i) {
        int m = bm + ty * 8 + i;
        if (m >= M) break;
#pragma unroll
        for (int j = 0; j < 8; j += 4) {
            int n = bn + tx * 8 + j;
            float4 r;
            r.x = fmaxf(acc[i][j + 0] + bias[n + 0], 0.0f);
            r.y = fmaxf(acc[i][j + 1] + bias[n + 1], 0.0f);
            r.z = fmaxf(acc[i][j + 2] + bias[n + 2], 0.0f);
            r.w = fmaxf(acc[i][j + 3] + bias[n + 3], 0.0f);
            *(float4*)(C + (long long)m * HDIM + n) = r;
        }
    }
}

// ---------------- output head: sigmoid(h2 @ Wo^T + bo) ----------------
__global__ void head_kernel(const float* __restrict__ h2,
                            const float* __restrict__ Wo,
                            const float* __restrict__ bo,
                            float* __restrict__ out, int M) {
    __shared__ float w[HDIM];
    for (int i = threadIdx.x; i < HDIM; i += blockDim.x) w[i] = Wo[i];
    __syncthreads();

    int gwarp = (blockIdx.x * blockDim.x + threadIdx.x) >> 5;
    int lane  = threadIdx.x & 31;
    if (gwarp >= M) return;

    const float* row = h2 + (long long)gwarp * HDIM;
    float s = 0.0f;
#pragma unroll
    for (int t = 0; t < HDIM / 32; ++t) {
        int idx = lane + t * 32;
        s += row[idx] * w[idx];
    }
#pragma unroll
    for (int o = 16; o; o >>= 1) s += __shfl_xor_sync(0xffffffffu, s, o);
    if (lane == 0) {
        float z = s + bo[0];
        out[gwarp] = 1.0f / (1.0f + expf(-z));
    }
}

// ---------------- launch ----------------

extern "C" void kernel_launch(void* const* d_in, const int* in_sizes, int n_in,
                              void* d_out, int out_size) {
    const float* x  = (const float*)d_in[0];
    const int*   ei = (const int*)  d_in[1];
    const float* W1 = (const float*)d_in[2];
    const float* b1 = (const float*)d_in[3];
    const float* W2 = (const float*)d_in[4];
    const float* b2 = (const float*)d_in[5];
    const float* Wo = (const float*)d_in[6];
    const float* bo = (const float*)d_in[7];
    float* out = (float*)d_out;

    const int N = in_sizes[0] / FDIM;
    const int E = in_sizes[1] / 2;
    const int* src = ei;
    const int* dst = ei + E;

    float *deg, *agg, *h1, *h2;
    cudaGetSymbolAddress((void**)&deg, g_deg);
    cudaGetSymbolAddress((void**)&agg, g_agg);
    cudaGetSymbolAddress((void**)&h1,  g_h1);
    cudaGetSymbolAddress((void**)&h2,  g_h2);

    const int T = 256;

    // degree + inverse
    zero1_kernel<<<(N + T - 1) / T, T>>>(deg, N);
    deg_kernel<<<(E + T - 1) / T, T>>>(dst, E, deg);
    invdeg_kernel<<<(N + T - 1) / T, T>>>(deg, N);

    // ---- layer 1 aggregation (D = 128, D4 = 32) ----
    {
        int n4 = N * FDIM / 4;
        zero4_kernel<<<(n4 + T - 1) / T, T>>>((float4*)agg, n4);
        long long total = (long long)E * (FDIM / 4);
        int blocks = (int)((total + T - 1) / T);
        scatter_kernel<<<blocks, T>>>(x, src, dst, agg, total, 5);
    }
    // ---- layer 1 GEMM: h1 = relu([x, n1] @ W1^T + b1) ----
    {
        dim3 grid((N + 127) / 128, HDIM / 128);
        gemm_cat_relu<<<grid, 256>>>(x, agg, deg, W1, b1, h1, N, FDIM);
    }

    // ---- layer 2 aggregation (D = 512, D4 = 128) ----
    {
        int n4 = N * HDIM / 4;
        zero4_kernel<<<(n4 + T - 1) / T, T>>>((float4*)agg, n4);
        long long total = (long long)E * (HDIM / 4);
        int blocks = (int)((total + T - 1) / T);
        scatter_kernel<<<blocks, T>>>(h1, src, dst, agg, total, 7);
    }
    // ---- layer 2 GEMM: h2 = relu([h1, n2] @ W2^T + b2) ----
    {
        dim3 grid((N + 127) / 128, HDIM / 128);
        gemm_cat_relu<<<grid, 256>>>(h1, agg, deg, W2, b2, h2, N, HDIM);
    }

    // ---- output head ----
    head_kernel<<<(N * 32 + T - 1) / T, T>>>(h2, Wo, bo, out, N);
}

// round 3
// speedup vs baseline: 2.1407x; 2.1407x over previous
#include <cuda_runtime.h>
#include <cuda_bf16.h>
#include <cstdint>
#include <math.h>

// ---------------------------------------------------------------------------
// GraphSAGE fraud detector — round 3.
//  * GEMMs via mma.sync bf16 (m16n8k16, HMMA fallback path — tcgen05 PTX is
//    rejected by this toolchain's sm_103 (non-'a') ptxas target).
//  * Split precision: A,W = hi + lo bf16; acc = hi*hi + hi*lo + lo*hi (fp32).
//  * Edge scatter uses red.global.add.v4.f32.
// N<=50048 nodes, F=128, H=512. Scratch in __device__ globals (no allocs).
// ---------------------------------------------------------------------------

#define MAXN 50048
#define HDIM 512
#define FDIM 128

__device__ __align__(16) float g_deg[MAXN];                 // degree -> 1/max(deg,1)
__device__ __align__(16) float g_agg[(size_t)MAXN * HDIM];  // reused both layers
__device__ __align__(16) float g_h1 [(size_t)MAXN * HDIM];
__device__ __align__(16) float g_h2 [(size_t)MAXN * HDIM];
__device__ __align__(16) __nv_bfloat16 g_whi[(size_t)HDIM * 1024];
__device__ __align__(16) __nv_bfloat16 g_wlo[(size_t)HDIM * 1024];

// ======================= helpers =============================

__device__ __forceinline__ uint32_t smem_u32(const void* p) {
    uint32_t a;
    asm("{ .reg .u64 t; cvta.to.shared.u64 t, %1; cvt.u32.u64 %0, t; }"
        : "=r"(a) : "l"(p));
    return a;
}

__device__ __forceinline__ void ldsm4(uint32_t* r, uint32_t addr) {
    asm volatile("ldmatrix.sync.aligned.m8n8.x4.shared.b16 {%0,%1,%2,%3}, [%4];"
                 : "=r"(r[0]), "=r"(r[1]), "=r"(r[2]), "=r"(r[3]) : "r"(addr));
}

__device__ __forceinline__ void mma16816(float* d, const uint32_t* a, const uint32_t* b) {
    asm volatile(
        "mma.sync.aligned.m16n8k16.row.col.f32.bf16.bf16.f32 "
        "{%0,%1,%2,%3}, {%4,%5,%6,%7}, {%8,%9}, {%0,%1,%2,%3};"
        : "+f"(d[0]), "+f"(d[1]), "+f"(d[2]), "+f"(d[3])
        : "r"(a[0]), "r"(a[1]), "r"(a[2]), "r"(a[3]), "r"(b[0]), "r"(b[1]));
}

__device__ __forceinline__ uint32_t pack_bf2(float lo_elem, float hi_elem) {
    __nv_bfloat162 h = __floats2bfloat162_rn(lo_elem, hi_elem);
    return *(uint32_t*)&h;
}

// ======================= small utility kernels =============================

__global__ void zero1_kernel(float* __restrict__ p, int n) {
    int i = blockIdx.x * blockDim.x + threadIdx.x;
    if (i < n) p[i] = 0.0f;
}

__global__ void zero4_kernel(float4* __restrict__ p, int n4) {
    int i = blockIdx.x * blockDim.x + threadIdx.x;
    if (i < n4) p[i] = make_float4(0.f, 0.f, 0.f, 0.f);
}

__global__ void deg_kernel(const int* __restrict__ dst, int E, float* __restrict__ deg) {
    int e = blockIdx.x * blockDim.x + threadIdx.x;
    if (e < E) atomicAdd(&deg[dst[e]], 1.0f);
}

__global__ void invdeg_kernel(float* __restrict__ deg, int n) {
    int i = blockIdx.x * blockDim.x + threadIdx.x;
    if (i < n) deg[i] = 1.0f / fmaxf(deg[i], 1.0f);
}

// Split fp32 weights into bf16 hi/lo pair.
__global__ void wsplit_kernel(const float* __restrict__ W,
                              __nv_bfloat16* __restrict__ hi,
                              __nv_bfloat16* __restrict__ lo, int n) {
    int i = blockIdx.x * blockDim.x + threadIdx.x;
    if (i < n) {
        float w = W[i];
        __nv_bfloat16 h = __float2bfloat16(w);
        hi[i] = h;
        lo[i] = __float2bfloat16(w - __bfloat162float(h));
    }
}

// ---------------- edge scatter: agg[dst] += feat[src] ----------------
__global__ void scatter_kernel(const float* __restrict__ feat,
                               const int* __restrict__ src,
                               const int* __restrict__ dst,
                               float4* __restrict__ outbuf,
                               long long total, int log2d4) {
    long long t = (long long)blockIdx.x * blockDim.x + threadIdx.x;
    if (t >= total) return;
    int d4mask = (1 << log2d4) - 1;
    int e = (int)(t >> log2d4);
    int c = (int)t & d4mask;
    int s = src[e];
    int d = dst[e];
    int D4 = 1 << log2d4;
    float4 v = ((const float4*)feat)[(long long)s * D4 + c];
    float4* o = outbuf + ((long long)d * D4 + c);
    asm volatile("red.global.add.v4.f32 [%0], {%1, %2, %3, %4};"
                 :: "l"(o), "f"(v.x), "f"(v.y), "f"(v.z), "f"(v.w) : "memory");
}

// =================== mma.sync fused concat-GEMM + bias + ReLU ===============
// C[m, n] = relu( sum_k concat(A1[m,:], A2[m,:]*invd[m])[k] * W[n, k] + bias[n] )
// CTA tile 128(M) x 128(N); 8 warps, each 64(M) x 32(N); K chunks of 32.
// Smem per chunk: A/B buffers 128 rows x 128B (hi in 16B cols 0-3, lo in 4-7),
// SW128 swizzle: addr = row*128 + ((c ^ (row&7))<<4) — conflict-free ldmatrix.

__global__ void __launch_bounds__(256)
gemm_tc(const float* __restrict__ A1, const float* __restrict__ A2,
        const float* __restrict__ invd,
        const __nv_bfloat16* __restrict__ Whi,
        const __nv_bfloat16* __restrict__ Wlo,
        const float* __restrict__ bias, float* __restrict__ C,
        int M, int Kh) {
    __shared__ __align__(128) uint8_t sA[128 * 128];
    __shared__ __align__(128) uint8_t sB[128 * 128];
    const uint32_t sbA = smem_u32(sA);
    const uint32_t sbB = smem_u32(sB);

    const int tid  = threadIdx.x;
    const int wid  = tid >> 5;
    const int lane = tid & 31;
    const int wm   = wid & 1;        // 0..1  -> 64-row band
    const int wn   = wid >> 1;       // 0..3  -> 32-col band
    const int K    = 2 * Kh;
    const int m0   = blockIdx.x * 128;
    const int n0   = blockIdx.y * 128;

    // ---- loader mapping: thread covers (row = tid>>1, 16 k at half*16) ----
    const int lrow = tid >> 1;
    const int half = tid & 1;
    const int kbase = half * 16;

    // ---- ldmatrix lane mapping ----
    const int qrow = lane & 15;      // row within 16-row tile
    const int qsel = lane >> 4;      // +0/+1 16B col (k+8 halves)

    float acc[4][4][4];
#pragma unroll
    for (int i = 0; i < 4; ++i)
#pragma unroll
        for (int j = 0; j < 4; ++j)
#pragma unroll
            for (int r = 0; r < 4; ++r) acc[i][j][r] = 0.0f;

    const int nch = K >> 5;

    float4 av[4];
    uint4  bhv[2], blv[2];
    float  asc = 1.0f;

    // ---- gmem load of chunk ch into regs ----
    auto load_regs = [&](int ch) {
        const int k0 = ch << 5;
        const int m  = m0 + lrow;
        const bool useA2 = (k0 >= Kh);
        asc = 1.0f;
        if (m < M) {
            const float* sp = (useA2 ? A2 : A1)
                              + (long long)m * Kh + (useA2 ? k0 - Kh : k0) + kbase;
            if (useA2) asc = invd[m];
#pragma unroll
            for (int q = 0; q < 4; ++q) av[q] = *(const float4*)(sp + q * 4);
        } else {
#pragma unroll
            for (int q = 0; q < 4; ++q) av[q] = make_float4(0.f, 0.f, 0.f, 0.f);
        }
        const int n = n0 + lrow;   // always < 512
        const uint4* ph = (const uint4*)(Whi + (long long)n * K + k0 + kbase);
        const uint4* pl = (const uint4*)(Wlo + (long long)n * K + k0 + kbase);
        bhv[0] = ph[0]; bhv[1] = ph[1];
        blv[0] = pl[0]; blv[1] = pl[1];
    };

    // ---- convert + store regs into smem ----
    auto store_smem = [&]() {
#pragma unroll
        for (int j = 0; j < 2; ++j) {
            float4 v0 = av[2 * j], v1 = av[2 * j + 1];
            v0.x *= asc; v0.y *= asc; v0.z *= asc; v0.w *= asc;
            v1.x *= asc; v1.y *= asc; v1.z *= asc; v1.w *= asc;
            __nv_bfloat16 h[8];
            h[0] = __float2bfloat16(v0.x); h[1] = __float2bfloat16(v0.y);
            h[2] = __float2bfloat16(v0.z); h[3] = __float2bfloat16(v0.w);
            h[4] = __float2bfloat16(v1.x); h[5] = __float2bfloat16(v1.y);
            h[6] = __float2bfloat16(v1.z); h[7] = __float2bfloat16(v1.w);
            uint4 uh, ul;
            uh.x = pack_bf2(__bfloat162float(h[0]), __bfloat162float(h[1]));
            uh.y = pack_bf2(__bfloat162float(h[2]), __bfloat162float(h[3]));
            uh.z = pack_bf2(__bfloat162float(h[4]), __bfloat162float(h[5]));
            uh.w = pack_bf2(__bfloat162float(h[6]), __bfloat162float(h[7]));
            ul.x = pack_bf2(v0.x - __bfloat162float(h[0]), v0.y - __bfloat162float(h[1]));
            ul.y = pack_bf2(v0.z - __bfloat162float(h[2]), v0.w - __bfloat162float(h[3]));
            ul.z = pack_bf2(v1.x - __bfloat162float(h[4]), v1.y - __bfloat162float(h[5]));
            ul.w = pack_bf2(v1.z - __bfloat162float(h[6]), v1.w - __bfloat162float(h[7]));
            const int chi = half * 2 + j;
            const int clo = 4 + half * 2 + j;
            *(uint4*)(sA + lrow * 128 + ((chi ^ (lrow & 7)) << 4)) = uh;
            *(uint4*)(sA + lrow * 128 + ((clo ^ (lrow & 7)) << 4)) = ul;
            *(uint4*)(sB + lrow * 128 + ((chi ^ (lrow & 7)) << 4)) = bhv[j];
            *(uint4*)(sB + lrow * 128 + ((clo ^ (lrow & 7)) << 4)) = blv[j];
        }
    };

    load_regs(0);
    store_smem();
    __syncthreads();

    for (int ch = 0; ch < nch; ++ch) {
        const bool more = (ch + 1 < nch);
        if (more) load_regs(ch + 1);

        // ---- compute on smem chunk (two k16 steps) ----
#pragma unroll
        for (int s = 0; s < 2; ++s) {
            uint32_t ah[4][4], al[4][4], bh[2][4], bl[2][4];
#pragma unroll
            for (int i = 0; i < 4; ++i) {
                const int row = wm * 64 + i * 16 + qrow;
                const int chi = s * 2 + qsel;
                const int clo = 4 + s * 2 + qsel;
                ldsm4(ah[i], sbA + row * 128 + ((chi ^ (row & 7)) << 4));
                ldsm4(al[i], sbA + row * 128 + ((clo ^ (row & 7)) << 4));
            }
#pragma unroll
            for (int p = 0; p < 2; ++p) {
                const int row = wn * 32 + p * 16 + qrow;
                const int chi = s * 2 + qsel;
                const int clo = 4 + s * 2 + qsel;
                ldsm4(bh[p], sbB + row * 128 + ((chi ^ (row & 7)) << 4));
                ldsm4(bl[p], sbB + row * 128 + ((clo ^ (row & 7)) << 4));
            }
            // b fragments: tile 2p -> {r0, r2}, tile 2p+1 -> {r1, r3}
#pragma unroll
            for (int i = 0; i < 4; ++i) {
#pragma unroll
                for (int p = 0; p < 2; ++p) {
                    uint32_t f0h[2] = { bh[p][0], bh[p][2] };
                    uint32_t f1h[2] = { bh[p][1], bh[p][3] };
                    uint32_t f0l[2] = { bl[p][0], bl[p][2] };
                    uint32_t f1l[2] = { bl[p][1], bl[p][3] };
                    mma16816(acc[i][2 * p],     ah[i], f0h);
                    mma16816(acc[i][2 * p + 1], ah[i], f1h);
                    mma16816(acc[i][2 * p],     ah[i], f0l);
                    mma16816(acc[i][2 * p + 1], ah[i], f1l);
                    mma16816(acc[i][2 * p],     al[i], f0h);
                    mma16816(acc[i][2 * p + 1], al[i], f1h);
                }
            }
        }

        __syncthreads();
        if (more) {
            store_smem();
            __syncthreads();
        }
    }

    // ---- epilogue: bias + ReLU, float2 stores ----
#pragma unroll
    for (int j = 0; j < 4; ++j) {
        const int nb = n0 + wn * 32 + j * 8 + (lane & 3) * 2;
        const float b0 = bias[nb], b1 = bias[nb + 1];
#pragma unroll
        for (int i = 0; i < 4; ++i) {
            const int r0 = m0 + wm * 64 + i * 16 + (lane >> 2);
            if (r0 < M) {
                float2 o;
                o.x = fmaxf(acc[i][j][0] + b0, 0.f);
                o.y = fmaxf(acc[i][j][1] + b1, 0.f);
                *(float2*)(C + (long long)r0 * HDIM + nb) = o;
            }
            const int r1 = r0 + 8;
            if (r1 < M) {
                float2 o;
                o.x = fmaxf(acc[i][j][2] + b0, 0.f);
                o.y = fmaxf(acc[i][j][3] + b1, 0.f);
                *(float2*)(C + (long long)r1 * HDIM + nb) = o;
            }
        }
    }
}

// ---------------- output head: sigmoid(h2 @ Wo^T + bo) ----------------
__global__ void head_kernel(const float* __restrict__ h2,
                            const float* __restrict__ Wo,
                            const float* __restrict__ bo,
                            float* __restrict__ out, int M) {
    __shared__ float w[HDIM];
    for (int i = threadIdx.x; i < HDIM; i += blockDim.x) w[i] = Wo[i];
    __syncthreads();

    int gwarp = (blockIdx.x * blockDim.x + threadIdx.x) >> 5;
    int lane  = threadIdx.x & 31;
    if (gwarp >= M) return;

    const float* row = h2 + (long long)gwarp * HDIM;
    float s = 0.0f;
#pragma unroll
    for (int t = 0; t < HDIM / 32; ++t) {
        int idx = lane + t * 32;
        s += row[idx] * w[idx];
    }
#pragma unroll
    for (int o = 16; o; o >>= 1) s += __shfl_xor_sync(0xffffffffu, s, o);
    if (lane == 0) {
        float z = s + bo[0];
        out[gwarp] = 1.0f / (1.0f + expf(-z));
    }
}

// ---------------- launch ----------------

extern "C" void kernel_launch(void* const* d_in, const int* in_sizes, int n_in,
                              void* d_out, int out_size) {
    const float* x  = (const float*)d_in[0];
    const int*   ei = (const int*)  d_in[1];
    const float* W1 = (const float*)d_in[2];
    const float* b1 = (const float*)d_in[3];
    const float* W2 = (const float*)d_in[4];
    const float* b2 = (const float*)d_in[5];
    const float* Wo = (const float*)d_in[6];
    const float* bo = (const float*)d_in[7];
    float* out = (float*)d_out;

    const int N = in_sizes[0] / FDIM;
    const int E = in_sizes[1] / 2;
    const int* src = ei;
    const int* dst = ei + E;

    float *deg, *agg, *h1, *h2;
    __nv_bfloat16 *whi, *wlo;
    cudaGetSymbolAddress((void**)&deg, g_deg);
    cudaGetSymbolAddress((void**)&agg, g_agg);
    cudaGetSymbolAddress((void**)&h1,  g_h1);
    cudaGetSymbolAddress((void**)&h2,  g_h2);
    cudaGetSymbolAddress((void**)&whi, g_whi);
    cudaGetSymbolAddress((void**)&wlo, g_wlo);

    const int T = 256;

    // degree + inverse
    zero1_kernel<<<(N + T - 1) / T, T>>>(deg, N);
    deg_kernel<<<(E + T - 1) / T, T>>>(dst, E, deg);
    invdeg_kernel<<<(N + T - 1) / T, T>>>(deg, N);

    // ---- layer 1 ----
    {
        int nw = HDIM * 2 * FDIM;
        wsplit_kernel<<<(nw + T - 1) / T, T>>>(W1, whi, wlo, nw);

        int n4 = N * FDIM / 4;
        zero4_kernel<<<(n4 + T - 1) / T, T>>>((float4*)agg, n4);
        long long total = (long long)E * (FDIM / 4);
        scatter_kernel<<<(int)((total + T - 1) / T), T>>>(x, src, dst, (float4*)agg, total, 5);

        dim3 grid((N + 127) / 128, HDIM / 128);
        gemm_tc<<<grid, 256>>>(x, agg, deg, whi, wlo, b1, h1, N, FDIM);
    }

    // ---- layer 2 ----
    {
        int nw = HDIM * 2 * HDIM;
        wsplit_kernel<<<(nw + T - 1) / T, T>>>(W2, whi, wlo, nw);

        int n4 = N * HDIM / 4;
        zero4_kernel<<<(n4 + T - 1) / T, T>>>((float4*)agg, n4);
        long long total = (long long)E * (HDIM / 4);
        scatter_kernel<<<(int)((total + T - 1) / T), T>>>(h1, src, dst, (float4*)agg, total, 7);

        dim3 grid((N + 127) / 128, HDIM / 128);
        gemm_tc<<<grid, 256>>>(h1, agg, deg, whi, wlo, b2, h2, N, HDIM);
    }

    // ---- output head ----
    head_kernel<<<(N * 32 + T - 1) / T, T>>>(h2, Wo, bo, out, N);
}

// round 4
// speedup vs baseline: 2.4281x; 1.1343x over previous
#include <cuda_runtime.h>
#include <cuda_bf16.h>
#include <cstdint>
#include <math.h>

// ---------------------------------------------------------------------------
// GraphSAGE fraud detector — round 4.
//  * CSR-gather aggregation (no atomics on features, no zero-fill).
//  * GEMMs via mma.sync bf16 split precision (hi*hi + hi*lo + lo*hi).
//  * Output head fused into GEMM2 epilogue (h2 never materialized).
// ---------------------------------------------------------------------------

#define MAXN 50048
#define MAXE 409600
#define HDIM 512
#define FDIM 128

__device__ __align__(16) float g_inv[MAXN];                 // 1/max(deg,1)
__device__ __align__(16) float g_agg[(size_t)MAXN * HDIM];  // reused both layers
__device__ __align__(16) float g_h1 [(size_t)MAXN * HDIM];
__device__ __align__(16) __nv_bfloat16 g_whi[(size_t)HDIM * 1024];
__device__ __align__(16) __nv_bfloat16 g_wlo[(size_t)HDIM * 1024];
__device__ int g_cnt[MAXN];        // histogram, then running fill position
__device__ int g_off[MAXN + 1];    // CSR offsets
__device__ int g_eid[MAXE];        // src node per (dst-sorted) edge

// ======================= helpers =============================

__device__ __forceinline__ uint32_t smem_u32(const void* p) {
    uint32_t a;
    asm("{ .reg .u64 t; cvta.to.shared.u64 t, %1; cvt.u32.u64 %0, t; }"
        : "=r"(a) : "l"(p));
    return a;
}

__device__ __forceinline__ void ldsm4(uint32_t* r, uint32_t addr) {
    asm volatile("ldmatrix.sync.aligned.m8n8.x4.shared.b16 {%0,%1,%2,%3}, [%4];"
                 : "=r"(r[0]), "=r"(r[1]), "=r"(r[2]), "=r"(r[3]) : "r"(addr));
}

__device__ __forceinline__ void mma16816(float* d, const uint32_t* a, const uint32_t* b) {
    asm volatile(
        "mma.sync.aligned.m16n8k16.row.col.f32.bf16.bf16.f32 "
        "{%0,%1,%2,%3}, {%4,%5,%6,%7}, {%8,%9}, {%0,%1,%2,%3};"
        : "+f"(d[0]), "+f"(d[1]), "+f"(d[2]), "+f"(d[3])
        : "r"(a[0]), "r"(a[1]), "r"(a[2]), "r"(a[3]), "r"(b[0]), "r"(b[1]));
}

__device__ __forceinline__ uint32_t pack_bf2(float a, float b) {
    __nv_bfloat162 h = __floats2bfloat162_rn(a, b);
    return *(uint32_t*)&h;
}

// ======================= CSR build =============================

__global__ void zeroi_kernel(int* __restrict__ p, int n) {
    int i = blockIdx.x * blockDim.x + threadIdx.x;
    if (i < n) p[i] = 0;
}

__global__ void count_kernel(const int* __restrict__ dst, int E, int* __restrict__ cnt) {
    int e = blockIdx.x * blockDim.x + threadIdx.x;
    if (e < E) atomicAdd(&cnt[dst[e]], 1);
}

// Single-block exclusive scan of cnt[0..n) -> off[0..n], off[n]=total.
// Also writes inv[d] = 1/max(cnt[d],1).
__global__ void scan_kernel(const int* __restrict__ cnt, int* __restrict__ off,
                            float* __restrict__ inv, int n) {
    __shared__ int s[1024];
    const int t = threadIdx.x;
    const int chunk = (n + 1023) >> 10;
    const int start = t * chunk;
    const int end   = min(start + chunk, n);

    int sum = 0;
    for (int i = start; i < end; ++i) sum += cnt[i];
    s[t] = sum;
    __syncthreads();
#pragma unroll
    for (int o = 1; o < 1024; o <<= 1) {
        int v = (t >= o) ? s[t - o] : 0;
        __syncthreads();
        s[t] += v;
        __syncthreads();
    }
    int run = (t == 0) ? 0 : s[t - 1];
    for (int i = start; i < end; ++i) {
        off[i] = run;
        int c = cnt[i];
        inv[i] = 1.0f / fmaxf((float)c, 1.0f);
        run += c;
    }
    if (t == 0) off[n] = s[1023];
}

__global__ void fill_kernel(const int* __restrict__ src, const int* __restrict__ dst,
                            int E, const int* __restrict__ off,
                            int* __restrict__ pos, int* __restrict__ eid) {
    int e = blockIdx.x * blockDim.x + threadIdx.x;
    if (e < E) {
        int d = dst[e];
        int p = atomicAdd(&pos[d], 1);
        eid[off[d] + p] = src[e];
    }
}

// ---------------- CSR gather: agg[d] = mean over incoming of feat[src] -----
// D4 threads per dst node; each thread owns one float4 column.
template <int D4>
__global__ void gather_kernel(const float* __restrict__ feat,
                              const int* __restrict__ off,
                              const int* __restrict__ eid,
                              const float* __restrict__ inv,
                              float* __restrict__ outp, int N) {
    const int gpb = blockDim.x / D4;
    const int g = blockIdx.x * gpb + threadIdx.x / D4;
    const int c = threadIdx.x % D4;
    if (g >= N) return;
    const int b  = off[g];
    const int e2 = off[g + 1];
    float4 acc = make_float4(0.f, 0.f, 0.f, 0.f);
    for (int j = b; j < e2; ++j) {
        int s = __ldg(&eid[j]);
        float4 v = __ldg(&((const float4*)feat)[(long long)s * D4 + c]);
        acc.x += v.x; acc.y += v.y; acc.z += v.z; acc.w += v.w;
    }
    const float sc = inv[g];
    acc.x *= sc; acc.y *= sc; acc.z *= sc; acc.w *= sc;
    ((float4*)outp)[(long long)g * D4 + c] = acc;
}

// Split fp32 weights into bf16 hi/lo pair.
__global__ void wsplit_kernel(const float* __restrict__ W,
                              __nv_bfloat16* __restrict__ hi,
                              __nv_bfloat16* __restrict__ lo, int n) {
    int i = blockIdx.x * blockDim.x + threadIdx.x;
    if (i < n) {
        float w = W[i];
        __nv_bfloat16 h = __float2bfloat16(w);
        hi[i] = h;
        lo[i] = __float2bfloat16(w - __bfloat162float(h));
    }
}

// =================== mma.sync fused concat-GEMM + bias + ReLU ===============
// C[m, n] = relu( sum_k concat(A1[m,:], A2mean[m,:])[k] * W[n, k] + bias[n] )
// CTA tile 128(M) x 128(N); 8 warps at 64x32; K chunks of 32.
// If Wo != nullptr: skip C store; instead accumulate logit partials
// sum_n relu(...)*Wo[n] into outLogit[m] via atomicAdd (head fusion).

__global__ void __launch_bounds__(256)
gemm_tc(const float* __restrict__ A1, const float* __restrict__ A2,
        const __nv_bfloat16* __restrict__ Whi,
        const __nv_bfloat16* __restrict__ Wlo,
        const float* __restrict__ bias, float* __restrict__ C,
        const float* __restrict__ Wo, float* __restrict__ outLogit,
        int M, int Kh) {
    __shared__ __align__(128) uint8_t sA[128 * 128];
    __shared__ __align__(128) uint8_t sB[128 * 128];
    const uint32_t sbA = smem_u32(sA);
    const uint32_t sbB = smem_u32(sB);

    const int tid  = threadIdx.x;
    const int wid  = tid >> 5;
    const int lane = tid & 31;
    const int wm   = wid & 1;
    const int wn   = wid >> 1;
    const int K    = 2 * Kh;
    const int m0   = blockIdx.x * 128;
    const int n0   = blockIdx.y * 128;

    const int lrow = tid >> 1;
    const int half = tid & 1;
    const int kbase = half * 16;

    const int qrow = lane & 15;
    const int qsel = lane >> 4;

    float acc[4][4][4];
#pragma unroll
    for (int i = 0; i < 4; ++i)
#pragma unroll
        for (int j = 0; j < 4; ++j)
#pragma unroll
            for (int r = 0; r < 4; ++r) acc[i][j][r] = 0.0f;

    const int nch = K >> 5;

    float4 av[4];
    uint4  bhv[2], blv[2];

    auto load_regs = [&](int ch) {
        const int k0 = ch << 5;
        const int m  = m0 + lrow;
        const bool useA2 = (k0 >= Kh);
        if (m < M) {
            const float* sp = (useA2 ? A2 : A1)
                              + (long long)m * Kh + (useA2 ? k0 - Kh : k0) + kbase;
#pragma unroll
            for (int q = 0; q < 4; ++q) av[q] = *(const float4*)(sp + q * 4);
        } else {
#pragma unroll
            for (int q = 0; q < 4; ++q) av[q] = make_float4(0.f, 0.f, 0.f, 0.f);
        }
        const int n = n0 + lrow;
        const uint4* ph = (const uint4*)(Whi + (long long)n * K + k0 + kbase);
        const uint4* pl = (const uint4*)(Wlo + (long long)n * K + k0 + kbase);
        bhv[0] = ph[0]; bhv[1] = ph[1];
        blv[0] = pl[0]; blv[1] = pl[1];
    };

    auto store_smem = [&]() {
#pragma unroll
        for (int j = 0; j < 2; ++j) {
            float4 v0 = av[2 * j], v1 = av[2 * j + 1];
            __nv_bfloat16 h[8];
            h[0] = __float2bfloat16(v0.x); h[1] = __float2bfloat16(v0.y);
            h[2] = __float2bfloat16(v0.z); h[3] = __float2bfloat16(v0.w);
            h[4] = __float2bfloat16(v1.x); h[5] = __float2bfloat16(v1.y);
            h[6] = __float2bfloat16(v1.z); h[7] = __float2bfloat16(v1.w);
            uint4 uh, ul;
            uh.x = pack_bf2(__bfloat162float(h[0]), __bfloat162float(h[1]));
            uh.y = pack_bf2(__bfloat162float(h[2]), __bfloat162float(h[3]));
            uh.z = pack_bf2(__bfloat162float(h[4]), __bfloat162float(h[5]));
            uh.w = pack_bf2(__bfloat162float(h[6]), __bfloat162float(h[7]));
            ul.x = pack_bf2(v0.x - __bfloat162float(h[0]), v0.y - __bfloat162float(h[1]));
            ul.y = pack_bf2(v0.z - __bfloat162float(h[2]), v0.w - __bfloat162float(h[3]));
            ul.z = pack_bf2(v1.x - __bfloat162float(h[4]), v1.y - __bfloat162float(h[5]));
            ul.w = pack_bf2(v1.z - __bfloat162float(h[6]), v1.w - __bfloat162float(h[7]));
            const int chi = half * 2 + j;
            const int clo = 4 + half * 2 + j;
            *(uint4*)(sA + lrow * 128 + ((chi ^ (lrow & 7)) << 4)) = uh;
            *(uint4*)(sA + lrow * 128 + ((clo ^ (lrow & 7)) << 4)) = ul;
            *(uint4*)(sB + lrow * 128 + ((chi ^ (lrow & 7)) << 4)) = bhv[j];
            *(uint4*)(sB + lrow * 128 + ((clo ^ (lrow & 7)) << 4)) = blv[j];
        }
    };

    load_regs(0);
    store_smem();
    __syncthreads();

    for (int ch = 0; ch < nch; ++ch) {
        const bool more = (ch + 1 < nch);
        if (more) load_regs(ch + 1);

#pragma unroll
        for (int s = 0; s < 2; ++s) {
            uint32_t ah[4][4], al[4][4], bh[2][4], bl[2][4];
#pragma unroll
            for (int i = 0; i < 4; ++i) {
                const int row = wm * 64 + i * 16 + qrow;
                const int chi = s * 2 + qsel;
                const int clo = 4 + s * 2 + qsel;
                ldsm4(ah[i], sbA + row * 128 + ((chi ^ (row & 7)) << 4));
                ldsm4(al[i], sbA + row * 128 + ((clo ^ (row & 7)) << 4));
            }
#pragma unroll
            for (int p = 0; p < 2; ++p) {
                const int row = wn * 32 + p * 16 + qrow;
                const int chi = s * 2 + qsel;
                const int clo = 4 + s * 2 + qsel;
                ldsm4(bh[p], sbB + row * 128 + ((chi ^ (row & 7)) << 4));
                ldsm4(bl[p], sbB + row * 128 + ((clo ^ (row & 7)) << 4));
            }
#pragma unroll
            for (int i = 0; i < 4; ++i) {
#pragma unroll
                for (int p = 0; p < 2; ++p) {
                    uint32_t f0h[2] = { bh[p][0], bh[p][2] };
                    uint32_t f1h[2] = { bh[p][1], bh[p][3] };
                    uint32_t f0l[2] = { bl[p][0], bl[p][2] };
                    uint32_t f1l[2] = { bl[p][1], bl[p][3] };
                    mma16816(acc[i][2 * p],     ah[i], f0h);
                    mma16816(acc[i][2 * p + 1], ah[i], f1h);
                    mma16816(acc[i][2 * p],     ah[i], f0l);
                    mma16816(acc[i][2 * p + 1], ah[i], f1l);
                    mma16816(acc[i][2 * p],     al[i], f0h);
                    mma16816(acc[i][2 * p + 1], al[i], f1h);
                }
            }
        }

        __syncthreads();
        if (more) {
            store_smem();
            __syncthreads();
        }
    }

    if (Wo == nullptr) {
        // ---- epilogue A: bias + ReLU -> C ----
#pragma unroll
        for (int j = 0; j < 4; ++j) {
            const int nb = n0 + wn * 32 + j * 8 + (lane & 3) * 2;
            const float b0 = bias[nb], b1 = bias[nb + 1];
#pragma unroll
            for (int i = 0; i < 4; ++i) {
                const int r0 = m0 + wm * 64 + i * 16 + (lane >> 2);
                if (r0 < M) {
                    float2 o;
                    o.x = fmaxf(acc[i][j][0] + b0, 0.f);
                    o.y = fmaxf(acc[i][j][1] + b1, 0.f);
                    *(float2*)(C + (long long)r0 * HDIM + nb) = o;
                }
                const int r1 = r0 + 8;
                if (r1 < M) {
                    float2 o;
                    o.x = fmaxf(acc[i][j][2] + b0, 0.f);
                    o.y = fmaxf(acc[i][j][3] + b1, 0.f);
                    *(float2*)(C + (long long)r1 * HDIM + nb) = o;
                }
            }
        }
    } else {
        // ---- epilogue B: fused head — partial logits ----
#pragma unroll
        for (int i = 0; i < 4; ++i) {
            float p0 = 0.f, p1 = 0.f;
#pragma unroll
            for (int j = 0; j < 4; ++j) {
                const int nb = n0 + wn * 32 + j * 8 + (lane & 3) * 2;
                const float b0 = bias[nb],  b1 = bias[nb + 1];
                const float w0 = __ldg(&Wo[nb]), w1 = __ldg(&Wo[nb + 1]);
                p0 += fmaxf(acc[i][j][0] + b0, 0.f) * w0
                    + fmaxf(acc[i][j][1] + b1, 0.f) * w1;
                p1 += fmaxf(acc[i][j][2] + b0, 0.f) * w0
                    + fmaxf(acc[i][j][3] + b1, 0.f) * w1;
            }
            p0 += __shfl_xor_sync(0xffffffffu, p0, 1);
            p0 += __shfl_xor_sync(0xffffffffu, p0, 2);
            p1 += __shfl_xor_sync(0xffffffffu, p1, 1);
            p1 += __shfl_xor_sync(0xffffffffu, p1, 2);
            if ((lane & 3) == 0) {
                const int r0 = m0 + wm * 64 + i * 16 + (lane >> 2);
                const int r1 = r0 + 8;
                if (r0 < M) atomicAdd(&outLogit[r0], p0);
                if (r1 < M) atomicAdd(&outLogit[r1], p1);
            }
        }
    }
}

// ---------------- head init / sigmoid ----------------
__global__ void initout_kernel(float* __restrict__ out, const float* __restrict__ bo, int n) {
    int i = blockIdx.x * blockDim.x + threadIdx.x;
    if (i < n) out[i] = bo[0];
}

__global__ void sigmoid_kernel(float* __restrict__ out, int n) {
    int i = blockIdx.x * blockDim.x + threadIdx.x;
    if (i < n) out[i] = 1.0f / (1.0f + expf(-out[i]));
}

// ---------------- launch ----------------

extern "C" void kernel_launch(void* const* d_in, const int* in_sizes, int n_in,
                              void* d_out, int out_size) {
    const float* x  = (const float*)d_in[0];
    const int*   ei = (const int*)  d_in[1];
    const float* W1 = (const float*)d_in[2];
    const float* b1 = (const float*)d_in[3];
    const float* W2 = (const float*)d_in[4];
    const float* b2 = (const float*)d_in[5];
    const float* Wo = (const float*)d_in[6];
    const float* bo = (const float*)d_in[7];
    float* out = (float*)d_out;

    const int N = in_sizes[0] / FDIM;
    const int E = in_sizes[1] / 2;
    const int* src = ei;
    const int* dst = ei + E;

    float *inv, *agg, *h1;
    __nv_bfloat16 *whi, *wlo;
    int *cnt, *off, *eid;
    cudaGetSymbolAddress((void**)&inv, g_inv);
    cudaGetSymbolAddress((void**)&agg, g_agg);
    cudaGetSymbolAddress((void**)&h1,  g_h1);
    cudaGetSymbolAddress((void**)&whi, g_whi);
    cudaGetSymbolAddress((void**)&wlo, g_wlo);
    cudaGetSymbolAddress((void**)&cnt, g_cnt);
    cudaGetSymbolAddress((void**)&off, g_off);
    cudaGetSymbolAddress((void**)&eid, g_eid);

    const int T = 256;

    // ---- CSR build ----
    zeroi_kernel<<<(N + T - 1) / T, T>>>(cnt, N);
    count_kernel<<<(E + T - 1) / T, T>>>(dst, E, cnt);
    scan_kernel<<<1, 1024>>>(cnt, off, inv, N);
    zeroi_kernel<<<(N + T - 1) / T, T>>>(cnt, N);
    fill_kernel<<<(E + T - 1) / T, T>>>(src, dst, E, off, cnt, eid);

    // ---- layer 1 ----
    {
        int nw = HDIM * 2 * FDIM;
        wsplit_kernel<<<(nw + T - 1) / T, T>>>(W1, whi, wlo, nw);
        // gather: 32 threads per dst, 8 dst per block
        gather_kernel<32><<<(N + 7) / 8, 256>>>(x, off, eid, inv, agg, N);
        dim3 grid((N + 127) / 128, HDIM / 128);
        gemm_tc<<<grid, 256>>>(x, agg, whi, wlo, b1, h1, nullptr, nullptr, N, FDIM);
    }

    // ---- layer 2 (head fused) ----
    {
        int nw = HDIM * 2 * HDIM;
        wsplit_kernel<<<(nw + T - 1) / T, T>>>(W2, whi, wlo, nw);
        // gather: 128 threads per dst, 2 dst per block
        gather_kernel<128><<<(N + 1) / 2, 256>>>(h1, off, eid, inv, agg, N);
        initout_kernel<<<(N + T - 1) / T, T>>>(out, bo, N);
        dim3 grid((N + 127) / 128, HDIM / 128);
        gemm_tc<<<grid, 256>>>(h1, agg, whi, wlo, b2, nullptr, Wo, out, N, HDIM);
    }

    sigmoid_kernel<<<(N + T - 1) / T, T>>>(out, N);
}

// round 5
// speedup vs baseline: 3.2020x; 1.3187x over previous
#include <cuda_runtime.h>
#include <cuda_bf16.h>
#include <cstdint>
#include <math.h>

// ---------------------------------------------------------------------------
// GraphSAGE fraud detector — round 5.
//  * Layer-2 activations (h1, agg2) stored as bf16: halves gather/GEMM2 A
//    traffic and removes the A lo-split term in GEMM2 (2 MMA terms, not 3).
//  * CSR-gather aggregation; head fused into GEMM2 epilogue.
// ---------------------------------------------------------------------------

#define MAXN 50048
#define MAXE 409600
#define HDIM 512
#define FDIM 128

__device__ __align__(16) float g_inv[MAXN];
__device__ __align__(16) float g_agg[(size_t)MAXN * FDIM];            // layer-1 mean (fp32)
__device__ __align__(16) __nv_bfloat16 g_h1 [(size_t)MAXN * HDIM];    // bf16
__device__ __align__(16) __nv_bfloat16 g_ag2[(size_t)MAXN * HDIM];    // bf16
__device__ __align__(16) __nv_bfloat16 g_whi[(size_t)HDIM * 1024];
__device__ __align__(16) __nv_bfloat16 g_wlo[(size_t)HDIM * 1024];
__device__ int g_cnt[MAXN];
__device__ int g_off[MAXN + 1];
__device__ int g_eid[MAXE];

// ======================= helpers =============================

__device__ __forceinline__ uint32_t smem_u32(const void* p) {
    uint32_t a;
    asm("{ .reg .u64 t; cvta.to.shared.u64 t, %1; cvt.u32.u64 %0, t; }"
        : "=r"(a) : "l"(p));
    return a;
}

__device__ __forceinline__ void ldsm4(uint32_t* r, uint32_t addr) {
    asm volatile("ldmatrix.sync.aligned.m8n8.x4.shared.b16 {%0,%1,%2,%3}, [%4];"
                 : "=r"(r[0]), "=r"(r[1]), "=r"(r[2]), "=r"(r[3]) : "r"(addr));
}

__device__ __forceinline__ void mma16816(float* d, const uint32_t* a, const uint32_t* b) {
    asm volatile(
        "mma.sync.aligned.m16n8k16.row.col.f32.bf16.bf16.f32 "
        "{%0,%1,%2,%3}, {%4,%5,%6,%7}, {%8,%9}, {%0,%1,%2,%3};"
        : "+f"(d[0]), "+f"(d[1]), "+f"(d[2]), "+f"(d[3])
        : "r"(a[0]), "r"(a[1]), "r"(a[2]), "r"(a[3]), "r"(b[0]), "r"(b[1]));
}

__device__ __forceinline__ uint32_t pack_bf2(float a, float b) {
    __nv_bfloat162 h = __floats2bfloat162_rn(a, b);
    return *(uint32_t*)&h;
}

// ======================= CSR build =============================

__global__ void zeroi_kernel(int* __restrict__ p, int n) {
    int i = blockIdx.x * blockDim.x + threadIdx.x;
    if (i < n) p[i] = 0;
}

__global__ void count_kernel(const int* __restrict__ dst, int E, int* __restrict__ cnt) {
    int e = blockIdx.x * blockDim.x + threadIdx.x;
    if (e < E) atomicAdd(&cnt[dst[e]], 1);
}

__global__ void scan_kernel(const int* __restrict__ cnt, int* __restrict__ off,
                            float* __restrict__ inv, int n) {
    __shared__ int s[1024];
    const int t = threadIdx.x;
    const int chunk = (n + 1023) >> 10;
    const int start = t * chunk;
    const int end   = min(start + chunk, n);

    int sum = 0;
    for (int i = start; i < end; ++i) sum += cnt[i];
    s[t] = sum;
    __syncthreads();
#pragma unroll
    for (int o = 1; o < 1024; o <<= 1) {
        int v = (t >= o) ? s[t - o] : 0;
        __syncthreads();
        s[t] += v;
        __syncthreads();
    }
    int run = (t == 0) ? 0 : s[t - 1];
    for (int i = start; i < end; ++i) {
        off[i] = run;
        int c = cnt[i];
        inv[i] = 1.0f / fmaxf((float)c, 1.0f);
        run += c;
    }
    if (t == 0) off[n] = s[1023];
}

__global__ void fill_kernel(const int* __restrict__ src, const int* __restrict__ dst,
                            int E, const int* __restrict__ off,
                            int* __restrict__ pos, int* __restrict__ eid) {
    int e = blockIdx.x * blockDim.x + threadIdx.x;
    if (e < E) {
        int d = dst[e];
        int p = atomicAdd(&pos[d], 1);
        eid[off[d] + p] = src[e];
    }
}

// ---------------- gather (fp32 features, layer 1): 32 thr/node -------------
__global__ void gather_f32(const float* __restrict__ feat,
                           const int* __restrict__ off,
                           const int* __restrict__ eid,
                           const float* __restrict__ inv,
                           float* __restrict__ outp, int N) {
    const int g = blockIdx.x * 8 + (threadIdx.x >> 5);
    const int c = threadIdx.x & 31;
    if (g >= N) return;
    const int b  = off[g];
    const int e2 = off[g + 1];
    float4 acc = make_float4(0.f, 0.f, 0.f, 0.f);
    for (int j = b; j < e2; ++j) {
        int s = __ldg(&eid[j]);
        float4 v = __ldg(&((const float4*)feat)[(long long)s * 32 + c]);
        acc.x += v.x; acc.y += v.y; acc.z += v.z; acc.w += v.w;
    }
    const float sc = inv[g];
    acc.x *= sc; acc.y *= sc; acc.z *= sc; acc.w *= sc;
    ((float4*)outp)[(long long)g * 32 + c] = acc;
}

// ---------------- gather (bf16 features, layer 2): 64 thr/node -------------
// Each thread owns 8 bf16 (one uint4). D = 512.
__global__ void gather_bf16(const __nv_bfloat16* __restrict__ feat,
                            const int* __restrict__ off,
                            const int* __restrict__ eid,
                            const float* __restrict__ inv,
                            __nv_bfloat16* __restrict__ outp, int N) {
    const int g = blockIdx.x * 4 + (threadIdx.x >> 6);
    const int c = threadIdx.x & 63;
    if (g >= N) return;
    const int b  = off[g];
    const int e2 = off[g + 1];
    float acc[8];
#pragma unroll
    for (int q = 0; q < 8; ++q) acc[q] = 0.f;
    const uint4* base = (const uint4*)feat;
    for (int j = b; j < e2; ++j) {
        int s = __ldg(&eid[j]);
        uint4 u = __ldg(&base[(long long)s * 64 + c]);
        float2 f;
        f = __bfloat1622float2(*(__nv_bfloat162*)&u.x); acc[0] += f.x; acc[1] += f.y;
        f = __bfloat1622float2(*(__nv_bfloat162*)&u.y); acc[2] += f.x; acc[3] += f.y;
        f = __bfloat1622float2(*(__nv_bfloat162*)&u.z); acc[4] += f.x; acc[5] += f.y;
        f = __bfloat1622float2(*(__nv_bfloat162*)&u.w); acc[6] += f.x; acc[7] += f.y;
    }
    const float sc = inv[g];
    uint4 o;
    o.x = pack_bf2(acc[0] * sc, acc[1] * sc);
    o.y = pack_bf2(acc[2] * sc, acc[3] * sc);
    o.z = pack_bf2(acc[4] * sc, acc[5] * sc);
    o.w = pack_bf2(acc[6] * sc, acc[7] * sc);
    ((uint4*)outp)[(long long)g * 64 + c] = o;
}

// Split fp32 weights into bf16 hi/lo pair.
__global__ void wsplit_kernel(const float* __restrict__ W,
                              __nv_bfloat16* __restrict__ hi,
                              __nv_bfloat16* __restrict__ lo, int n) {
    int i = blockIdx.x * blockDim.x + threadIdx.x;
    if (i < n) {
        float w = W[i];
        __nv_bfloat16 h = __float2bfloat16(w);
        hi[i] = h;
        lo[i] = __float2bfloat16(w - __bfloat162float(h));
    }
}

// =================== mma.sync fused concat-GEMM =============================
// MODE 0 (layer 1): A fp32, split hi/lo on the fly (3 MMA terms);
//                   epilogue bias+ReLU -> bf16 C.
// MODE 1 (layer 2): A bf16 (hi only, 2 MMA terms);
//                   epilogue fused head: logit partials -> atomicAdd outLogit.
// CTA tile 128(M) x 128(N); 8 warps at 64x32; K chunks of 32.

template <int MODE>
__global__ void __launch_bounds__(256)
gemm_tc(const void* __restrict__ A1v, const void* __restrict__ A2v,
        const __nv_bfloat16* __restrict__ Whi,
        const __nv_bfloat16* __restrict__ Wlo,
        const float* __restrict__ bias, __nv_bfloat16* __restrict__ C,
        const float* __restrict__ Wo, float* __restrict__ outLogit,
        int M, int Kh) {
    __shared__ __align__(128) uint8_t sA[128 * 128];
    __shared__ __align__(128) uint8_t sB[128 * 128];
    const uint32_t sbA = smem_u32(sA);
    const uint32_t sbB = smem_u32(sB);

    const int tid  = threadIdx.x;
    const int wid  = tid >> 5;
    const int lane = tid & 31;
    const int wm   = wid & 1;
    const int wn   = wid >> 1;
    const int K    = 2 * Kh;
    const int m0   = blockIdx.x * 128;
    const int n0   = blockIdx.y * 128;

    const int lrow = tid >> 1;
    const int half = tid & 1;
    const int kbase = half * 16;

    const int qrow = lane & 15;
    const int qsel = lane >> 4;

    float acc[4][4][4];
#pragma unroll
    for (int i = 0; i < 4; ++i)
#pragma unroll
        for (int j = 0; j < 4; ++j)
#pragma unroll
            for (int r = 0; r < 4; ++r) acc[i][j][r] = 0.0f;

    const int nch = K >> 5;

    float4 av[4];        // MODE 0 staging
    uint4  ahv[2];       // MODE 1 staging
    uint4  bhv[2], blv[2];

    auto load_regs = [&](int ch) {
        const int k0 = ch << 5;
        const int m  = m0 + lrow;
        const bool useA2 = (k0 >= Kh);
        const int koff = useA2 ? k0 - Kh : k0;
        if (MODE == 0) {
            if (m < M) {
                const float* sp = (const float*)(useA2 ? A2v : A1v)
                                  + (long long)m * Kh + koff + kbase;
#pragma unroll
                for (int q = 0; q < 4; ++q) av[q] = *(const float4*)(sp + q * 4);
            } else {
#pragma unroll
                for (int q = 0; q < 4; ++q) av[q] = make_float4(0.f, 0.f, 0.f, 0.f);
            }
        } else {
            if (m < M) {
                const __nv_bfloat16* sp = (const __nv_bfloat16*)(useA2 ? A2v : A1v)
                                          + (long long)m * Kh + koff + kbase;
                ahv[0] = ((const uint4*)sp)[0];
                ahv[1] = ((const uint4*)sp)[1];
            } else {
                ahv[0] = make_uint4(0u, 0u, 0u, 0u);
                ahv[1] = make_uint4(0u, 0u, 0u, 0u);
            }
        }
        const int n = n0 + lrow;
        const uint4* ph = (const uint4*)(Whi + (long long)n * K + k0 + kbase);
        const uint4* pl = (const uint4*)(Wlo + (long long)n * K + k0 + kbase);
        bhv[0] = ph[0]; bhv[1] = ph[1];
        blv[0] = pl[0]; blv[1] = pl[1];
    };

    auto store_smem = [&]() {
#pragma unroll
        for (int j = 0; j < 2; ++j) {
            const int chi = half * 2 + j;
            const int clo = 4 + half * 2 + j;
            if (MODE == 0) {
                float4 v0 = av[2 * j], v1 = av[2 * j + 1];
                __nv_bfloat16 h[8];
                h[0] = __float2bfloat16(v0.x); h[1] = __float2bfloat16(v0.y);
                h[2] = __float2bfloat16(v0.z); h[3] = __float2bfloat16(v0.w);
                h[4] = __float2bfloat16(v1.x); h[5] = __float2bfloat16(v1.y);
                h[6] = __float2bfloat16(v1.z); h[7] = __float2bfloat16(v1.w);
                uint4 uh, ul;
                uh.x = pack_bf2(__bfloat162float(h[0]), __bfloat162float(h[1]));
                uh.y = pack_bf2(__bfloat162float(h[2]), __bfloat162float(h[3]));
                uh.z = pack_bf2(__bfloat162float(h[4]), __bfloat162float(h[5]));
                uh.w = pack_bf2(__bfloat162float(h[6]), __bfloat162float(h[7]));
                ul.x = pack_bf2(v0.x - __bfloat162float(h[0]), v0.y - __bfloat162float(h[1]));
                ul.y = pack_bf2(v0.z - __bfloat162float(h[2]), v0.w - __bfloat162float(h[3]));
                ul.z = pack_bf2(v1.x - __bfloat162float(h[4]), v1.y - __bfloat162float(h[5]));
                ul.w = pack_bf2(v1.z - __bfloat162float(h[6]), v1.w - __bfloat162float(h[7]));
                *(uint4*)(sA + lrow * 128 + ((chi ^ (lrow & 7)) << 4)) = uh;
                *(uint4*)(sA + lrow * 128 + ((clo ^ (lrow & 7)) << 4)) = ul;
            } else {
                *(uint4*)(sA + lrow * 128 + ((chi ^ (lrow & 7)) << 4)) = ahv[j];
            }
            *(uint4*)(sB + lrow * 128 + ((chi ^ (lrow & 7)) << 4)) = bhv[j];
            *(uint4*)(sB + lrow * 128 + ((clo ^ (lrow & 7)) << 4)) = blv[j];
        }
    };

    load_regs(0);
    store_smem();
    __syncthreads();

    for (int ch = 0; ch < nch; ++ch) {
        const bool more = (ch + 1 < nch);
        if (more) load_regs(ch + 1);

#pragma unroll
        for (int s = 0; s < 2; ++s) {
            uint32_t ah[4][4], al[4][4], bh[2][4], bl[2][4];
#pragma unroll
            for (int i = 0; i < 4; ++i) {
                const int row = wm * 64 + i * 16 + qrow;
                const int chi = s * 2 + qsel;
                ldsm4(ah[i], sbA + row * 128 + ((chi ^ (row & 7)) << 4));
                if (MODE == 0) {
                    const int clo = 4 + s * 2 + qsel;
                    ldsm4(al[i], sbA + row * 128 + ((clo ^ (row & 7)) << 4));
                }
            }
#pragma unroll
            for (int p = 0; p < 2; ++p) {
                const int row = wn * 32 + p * 16 + qrow;
                const int chi = s * 2 + qsel;
                const int clo = 4 + s * 2 + qsel;
                ldsm4(bh[p], sbB + row * 128 + ((chi ^ (row & 7)) << 4));
                ldsm4(bl[p], sbB + row * 128 + ((clo ^ (row & 7)) << 4));
            }
#pragma unroll
            for (int i = 0; i < 4; ++i) {
#pragma unroll
                for (int p = 0; p < 2; ++p) {
                    uint32_t f0h[2] = { bh[p][0], bh[p][2] };
                    uint32_t f1h[2] = { bh[p][1], bh[p][3] };
                    uint32_t f0l[2] = { bl[p][0], bl[p][2] };
                    uint32_t f1l[2] = { bl[p][1], bl[p][3] };
                    mma16816(acc[i][2 * p],     ah[i], f0h);
                    mma16816(acc[i][2 * p + 1], ah[i], f1h);
                    mma16816(acc[i][2 * p],     ah[i], f0l);
                    mma16816(acc[i][2 * p + 1], ah[i], f1l);
                    if (MODE == 0) {
                        mma16816(acc[i][2 * p],     al[i], f0h);
                        mma16816(acc[i][2 * p + 1], al[i], f1h);
                    }
                }
            }
        }

        __syncthreads();
        if (more) {
            store_smem();
            __syncthreads();
        }
    }

    if (MODE == 0) {
        // ---- epilogue: bias + ReLU -> bf16 C ----
#pragma unroll
        for (int j = 0; j < 4; ++j) {
            const int nb = n0 + wn * 32 + j * 8 + (lane & 3) * 2;
            const float b0 = bias[nb], b1 = bias[nb + 1];
#pragma unroll
            for (int i = 0; i < 4; ++i) {
                const int r0 = m0 + wm * 64 + i * 16 + (lane >> 2);
                if (r0 < M) {
                    *(uint32_t*)(C + (long long)r0 * HDIM + nb) =
                        pack_bf2(fmaxf(acc[i][j][0] + b0, 0.f),
                                 fmaxf(acc[i][j][1] + b1, 0.f));
                }
                const int r1 = r0 + 8;
                if (r1 < M) {
                    *(uint32_t*)(C + (long long)r1 * HDIM + nb) =
                        pack_bf2(fmaxf(acc[i][j][2] + b0, 0.f),
                                 fmaxf(acc[i][j][3] + b1, 0.f));
                }
            }
        }
    } else {
        // ---- epilogue: fused head — partial logits ----
#pragma unroll
        for (int i = 0; i < 4; ++i) {
            float p0 = 0.f, p1 = 0.f;
#pragma unroll
            for (int j = 0; j < 4; ++j) {
                const int nb = n0 + wn * 32 + j * 8 + (lane & 3) * 2;
                const float b0 = bias[nb],  b1 = bias[nb + 1];
                const float w0 = __ldg(&Wo[nb]), w1 = __ldg(&Wo[nb + 1]);
                p0 += fmaxf(acc[i][j][0] + b0, 0.f) * w0
                    + fmaxf(acc[i][j][1] + b1, 0.f) * w1;
                p1 += fmaxf(acc[i][j][2] + b0, 0.f) * w0
                    + fmaxf(acc[i][j][3] + b1, 0.f) * w1;
            }
            p0 += __shfl_xor_sync(0xffffffffu, p0, 1);
            p0 += __shfl_xor_sync(0xffffffffu, p0, 2);
            p1 += __shfl_xor_sync(0xffffffffu, p1, 1);
            p1 += __shfl_xor_sync(0xffffffffu, p1, 2);
            if ((lane & 3) == 0) {
                const int r0 = m0 + wm * 64 + i * 16 + (lane >> 2);
                const int r1 = r0 + 8;
                if (r0 < M) atomicAdd(&outLogit[r0], p0);
                if (r1 < M) atomicAdd(&outLogit[r1], p1);
            }
        }
    }
}

// ---------------- head init / sigmoid ----------------
__global__ void initout_kernel(float* __restrict__ out, const float* __restrict__ bo, int n) {
    int i = blockIdx.x * blockDim.x + threadIdx.x;
    if (i < n) out[i] = bo[0];
}

__global__ void sigmoid_kernel(float* __restrict__ out, int n) {
    int i = blockIdx.x * blockDim.x + threadIdx.x;
    if (i < n) out[i] = 1.0f / (1.0f + expf(-out[i]));
}

// ---------------- launch ----------------

extern "C" void kernel_launch(void* const* d_in, const int* in_sizes, int n_in,
                              void* d_out, int out_size) {
    const float* x  = (const float*)d_in[0];
    const int*   ei = (const int*)  d_in[1];
    const float* W1 = (const float*)d_in[2];
    const float* b1 = (const float*)d_in[3];
    const float* W2 = (const float*)d_in[4];
    const float* b2 = (const float*)d_in[5];
    const float* Wo = (const float*)d_in[6];
    const float* bo = (const float*)d_in[7];
    float* out = (float*)d_out;

    const int N = in_sizes[0] / FDIM;
    const int E = in_sizes[1] / 2;
    const int* src = ei;
    const int* dst = ei + E;

    float *inv, *agg;
    __nv_bfloat16 *h1, *ag2, *whi, *wlo;
    int *cnt, *off, *eid;
    cudaGetSymbolAddress((void**)&inv, g_inv);
    cudaGetSymbolAddress((void**)&agg, g_agg);
    cudaGetSymbolAddress((void**)&h1,  g_h1);
    cudaGetSymbolAddress((void**)&ag2, g_ag2);
    cudaGetSymbolAddress((void**)&whi, g_whi);
    cudaGetSymbolAddress((void**)&wlo, g_wlo);
    cudaGetSymbolAddress((void**)&cnt, g_cnt);
    cudaGetSymbolAddress((void**)&off, g_off);
    cudaGetSymbolAddress((void**)&eid, g_eid);

    const int T = 256;

    // ---- CSR build ----
    zeroi_kernel<<<(N + T - 1) / T, T>>>(cnt, N);
    count_kernel<<<(E + T - 1) / T, T>>>(dst, E, cnt);
    scan_kernel<<<1, 1024>>>(cnt, off, inv, N);
    zeroi_kernel<<<(N + T - 1) / T, T>>>(cnt, N);
    fill_kernel<<<(E + T - 1) / T, T>>>(src, dst, E, off, cnt, eid);

    // ---- layer 1 ----
    {
        int nw = HDIM * 2 * FDIM;
        wsplit_kernel<<<(nw + T - 1) / T, T>>>(W1, whi, wlo, nw);
        gather_f32<<<(N + 7) / 8, 256>>>(x, off, eid, inv, agg, N);
        dim3 grid((N + 127) / 128, HDIM / 128);
        gemm_tc<0><<<grid, 256>>>(x, agg, whi, wlo, b1, h1, nullptr, nullptr, N, FDIM);
    }

    // ---- layer 2 (bf16 activations, head fused) ----
    {
        int nw = HDIM * 2 * HDIM;
        wsplit_kernel<<<(nw + T - 1) / T, T>>>(W2, whi, wlo, nw);
        gather_bf16<<<(N + 3) / 4, 256>>>(h1, off, eid, inv, ag2, N);
        initout_kernel<<<(N + T - 1) / T, T>>>(out, bo, N);
        dim3 grid((N + 127) / 128, HDIM / 128);
        gemm_tc<1><<<grid, 256>>>(h1, ag2, whi, wlo, b2, nullptr, Wo, out, N, HDIM);
    }

    sigmoid_kernel<<<(N + T - 1) / T, T>>>(out, N);
}

// round 6
// speedup vs baseline: 5.3567x; 1.6729x over previous
#include <cuda_runtime.h>
#include <cuda_fp16.h>
#include <cstdint>
#include <math.h>

// ---------------------------------------------------------------------------
// GraphSAGE fraud detector — round 6.
//  * All activations + weights in fp16 (2^-11 mantissa — 8x better than bf16
//    at the same byte cost). Single-term mma.sync f16 GEMMs (no hi/lo split).
//  * CSR-gather aggregation; output head fused into GEMM2 epilogue.
// ---------------------------------------------------------------------------

#define MAXN 50048
#define MAXE 409600
#define HDIM 512
#define FDIM 128

__device__ __align__(16) float  g_inv[MAXN];
__device__ __align__(16) __half g_xh [(size_t)MAXN * FDIM];
__device__ __align__(16) __half g_ag1[(size_t)MAXN * FDIM];
__device__ __align__(16) __half g_h1 [(size_t)MAXN * HDIM];
__device__ __align__(16) __half g_ag2[(size_t)MAXN * HDIM];
__device__ __align__(16) __half g_wh [(size_t)HDIM * 1024];
__device__ int g_cnt[MAXN];
__device__ int g_off[MAXN + 1];
__device__ int g_eid[MAXE];

// ======================= helpers =============================

__device__ __forceinline__ uint32_t smem_u32(const void* p) {
    uint32_t a;
    asm("{ .reg .u64 t; cvta.to.shared.u64 t, %1; cvt.u32.u64 %0, t; }"
        : "=r"(a) : "l"(p));
    return a;
}

__device__ __forceinline__ void ldsm4(uint32_t* r, uint32_t addr) {
    asm volatile("ldmatrix.sync.aligned.m8n8.x4.shared.b16 {%0,%1,%2,%3}, [%4];"
                 : "=r"(r[0]), "=r"(r[1]), "=r"(r[2]), "=r"(r[3]) : "r"(addr));
}

__device__ __forceinline__ void mma16816(float* d, const uint32_t* a, const uint32_t* b) {
    asm volatile(
        "mma.sync.aligned.m16n8k16.row.col.f32.f16.f16.f32 "
        "{%0,%1,%2,%3}, {%4,%5,%6,%7}, {%8,%9}, {%0,%1,%2,%3};"
        : "+f"(d[0]), "+f"(d[1]), "+f"(d[2]), "+f"(d[3])
        : "r"(a[0]), "r"(a[1]), "r"(a[2]), "r"(a[3]), "r"(b[0]), "r"(b[1]));
}

__device__ __forceinline__ uint32_t pack_h2(float a, float b) {
    __half2 h = __floats2half2_rn(a, b);
    return *(uint32_t*)&h;
}

// Tile addressing: 128 logical rows x 32 fp16 packed as 64 physical rows x
// 128B. Logical (r, c16) with c16 in [0,4): XOR-swizzled over 8 16B columns.
__device__ __forceinline__ uint32_t taddr(int r, int c16) {
    return (uint32_t)((r >> 1) * 128 + ((((r & 1) * 4 + c16) ^ ((r >> 1) & 7)) << 4));
}

// ======================= CSR build =============================

__global__ void zeroi_kernel(int* __restrict__ p, int n) {
    int i = blockIdx.x * blockDim.x + threadIdx.x;
    if (i < n) p[i] = 0;
}

__global__ void count_kernel(const int* __restrict__ dst, int E, int* __restrict__ cnt) {
    int e = blockIdx.x * blockDim.x + threadIdx.x;
    if (e < E) atomicAdd(&cnt[dst[e]], 1);
}

__global__ void scan_kernel(const int* __restrict__ cnt, int* __restrict__ off,
                            float* __restrict__ inv, int n) {
    __shared__ int s[1024];
    const int t = threadIdx.x;
    const int chunk = (n + 1023) >> 10;
    const int start = t * chunk;
    const int end   = min(start + chunk, n);

    int sum = 0;
    for (int i = start; i < end; ++i) sum += cnt[i];
    s[t] = sum;
    __syncthreads();
#pragma unroll
    for (int o = 1; o < 1024; o <<= 1) {
        int v = (t >= o) ? s[t - o] : 0;
        __syncthreads();
        s[t] += v;
        __syncthreads();
    }
    int run = (t == 0) ? 0 : s[t - 1];
    for (int i = start; i < end; ++i) {
        off[i] = run;
        int c = cnt[i];
        inv[i] = 1.0f / fmaxf((float)c, 1.0f);
        run += c;
    }
    if (t == 0) off[n] = s[1023];
}

__global__ void fill_kernel(const int* __restrict__ src, const int* __restrict__ dst,
                            int E, const int* __restrict__ off,
                            int* __restrict__ pos, int* __restrict__ eid) {
    int e = blockIdx.x * blockDim.x + threadIdx.x;
    if (e < E) {
        int d = dst[e];
        int p = atomicAdd(&pos[d], 1);
        eid[off[d] + p] = src[e];
    }
}

// ---------------- fp32 -> fp16 convert (vectorized) ----------------
__global__ void tohalf_kernel(const float* __restrict__ src, __half* __restrict__ dstp,
                              int n4) {
    int i = blockIdx.x * blockDim.x + threadIdx.x;
    if (i < n4) {
        float4 v = ((const float4*)src)[i];
        uint2 o;
        o.x = pack_h2(v.x, v.y);
        o.y = pack_h2(v.z, v.w);
        ((uint2*)dstp)[i] = o;
    }
}

// ---------------- CSR gather (fp16): mean of incoming features -------------
// U = uint4 (8 fp16) units per feature row; U threads per dst node.
template <int U>
__global__ void gather_f16(const __half* __restrict__ feat,
                           const int* __restrict__ off,
                           const int* __restrict__ eid,
                           const float* __restrict__ inv,
                           __half* __restrict__ outp, int N) {
    const int g = blockIdx.x * (256 / U) + threadIdx.x / U;
    const int c = threadIdx.x % U;
    if (g >= N) return;
    const int b  = off[g];
    const int e2 = off[g + 1];
    float acc[8];
#pragma unroll
    for (int q = 0; q < 8; ++q) acc[q] = 0.f;
    const uint4* base = (const uint4*)feat;
    for (int j = b; j < e2; ++j) {
        int s = __ldg(&eid[j]);
        uint4 u = __ldg(&base[(long long)s * U + c]);
        const __half2* h = (const __half2*)&u;
#pragma unroll
        for (int q = 0; q < 4; ++q) {
            float2 f = __half22float2(h[q]);
            acc[2 * q]     += f.x;
            acc[2 * q + 1] += f.y;
        }
    }
    const float sc = inv[g];
    uint4 o;
    o.x = pack_h2(acc[0] * sc, acc[1] * sc);
    o.y = pack_h2(acc[2] * sc, acc[3] * sc);
    o.z = pack_h2(acc[4] * sc, acc[5] * sc);
    o.w = pack_h2(acc[6] * sc, acc[7] * sc);
    ((uint4*)outp)[(long long)g * U + c] = o;
}

// =================== mma.sync fp16 concat-GEMM =============================
// C[m, n] = relu( sum_k concat(A1[m,:], A2[m,:])[k] * W[n, k] + bias[n] )
// A1, A2, W all fp16. CTA tile 128(M) x 128(N); 8 warps at 64x32; K chunks 32.
// FUSED 0: epilogue bias+ReLU -> fp16 C.
// FUSED 1: epilogue head: atomicAdd(outLogit[m], sum_n relu(.)*Wo[n]).

template <int FUSED>
__global__ void __launch_bounds__(256)
gemm_f16(const __half* __restrict__ A1, const __half* __restrict__ A2,
         const __half* __restrict__ W,
         const float* __restrict__ bias, __half* __restrict__ C,
         const float* __restrict__ Wo, float* __restrict__ outLogit,
         int M, int Kh) {
    __shared__ __align__(128) uint8_t sA[64 * 128];
    __shared__ __align__(128) uint8_t sB[64 * 128];
    const uint32_t sbA = smem_u32(sA);
    const uint32_t sbB = smem_u32(sB);

    const int tid  = threadIdx.x;
    const int wid  = tid >> 5;
    const int lane = tid & 31;
    const int wm   = wid & 1;
    const int wn   = wid >> 1;
    const int K    = 2 * Kh;
    const int m0   = blockIdx.x * 128;
    const int n0   = blockIdx.y * 128;

    const int lrow = tid >> 1;       // 0..127
    const int half = tid & 1;
    const int kbase = half * 16;     // 16 fp16 per loader thread

    const int qrow = lane & 15;
    const int qsel = lane >> 4;

    float acc[4][4][4];
#pragma unroll
    for (int i = 0; i < 4; ++i)
#pragma unroll
        for (int j = 0; j < 4; ++j)
#pragma unroll
            for (int r = 0; r < 4; ++r) acc[i][j][r] = 0.0f;

    const int nch = K >> 5;

    uint4 a0, a1, b0, b1;

    auto load_regs = [&](int ch) {
        const int k0 = ch << 5;
        const int m  = m0 + lrow;
        const bool useA2 = (k0 >= Kh);
        const int koff = (useA2 ? k0 - Kh : k0) + kbase;
        if (m < M) {
            const uint4* p = (const uint4*)((useA2 ? A2 : A1) + (long long)m * Kh + koff);
            a0 = p[0]; a1 = p[1];
        } else {
            a0 = make_uint4(0u, 0u, 0u, 0u);
            a1 = make_uint4(0u, 0u, 0u, 0u);
        }
        const int n = n0 + lrow;
        const uint4* q = (const uint4*)(W + (long long)n * K + k0 + kbase);
        b0 = q[0]; b1 = q[1];
    };

    auto store_smem = [&]() {
        const int c0 = half * 2, c1 = half * 2 + 1;
        *(uint4*)(sA + taddr(lrow, c0)) = a0;
        *(uint4*)(sA + taddr(lrow, c1)) = a1;
        *(uint4*)(sB + taddr(lrow, c0)) = b0;
        *(uint4*)(sB + taddr(lrow, c1)) = b1;
    };

    load_regs(0);
    store_smem();
    __syncthreads();

    for (int ch = 0; ch < nch; ++ch) {
        const bool more = (ch + 1 < nch);
        if (more) load_regs(ch + 1);

#pragma unroll
        for (int s = 0; s < 2; ++s) {
            uint32_t ah[4][4], bh[2][4];
            const int cc = s * 2 + qsel;
#pragma unroll
            for (int i = 0; i < 4; ++i) {
                const int row = wm * 64 + i * 16 + qrow;
                ldsm4(ah[i], sbA + taddr(row, cc));
            }
#pragma unroll
            for (int p = 0; p < 2; ++p) {
                const int row = wn * 32 + p * 16 + qrow;
                ldsm4(bh[p], sbB + taddr(row, cc));
            }
#pragma unroll
            for (int i = 0; i < 4; ++i) {
#pragma unroll
                for (int p = 0; p < 2; ++p) {
                    uint32_t f0[2] = { bh[p][0], bh[p][2] };
                    uint32_t f1[2] = { bh[p][1], bh[p][3] };
                    mma16816(acc[i][2 * p],     ah[i], f0);
                    mma16816(acc[i][2 * p + 1], ah[i], f1);
                }
            }
        }

        __syncthreads();
        if (more) {
            store_smem();
            __syncthreads();
        }
    }

    if (FUSED == 0) {
        // ---- epilogue: bias + ReLU -> fp16 C ----
#pragma unroll
        for (int j = 0; j < 4; ++j) {
            const int nb = n0 + wn * 32 + j * 8 + (lane & 3) * 2;
            const float b0f = bias[nb], b1f = bias[nb + 1];
#pragma unroll
            for (int i = 0; i < 4; ++i) {
                const int r0 = m0 + wm * 64 + i * 16 + (lane >> 2);
                if (r0 < M) {
                    *(uint32_t*)(C + (long long)r0 * HDIM + nb) =
                        pack_h2(fmaxf(acc[i][j][0] + b0f, 0.f),
                                fmaxf(acc[i][j][1] + b1f, 0.f));
                }
                const int r1 = r0 + 8;
                if (r1 < M) {
                    *(uint32_t*)(C + (long long)r1 * HDIM + nb) =
                        pack_h2(fmaxf(acc[i][j][2] + b0f, 0.f),
                                fmaxf(acc[i][j][3] + b1f, 0.f));
                }
            }
        }
    } else {
        // ---- epilogue: fused head — partial logits ----
#pragma unroll
        for (int i = 0; i < 4; ++i) {
            float p0 = 0.f, p1 = 0.f;
#pragma unroll
            for (int j = 0; j < 4; ++j) {
                const int nb = n0 + wn * 32 + j * 8 + (lane & 3) * 2;
                const float b0f = bias[nb],  b1f = bias[nb + 1];
                const float w0 = __ldg(&Wo[nb]), w1 = __ldg(&Wo[nb + 1]);
                p0 += fmaxf(acc[i][j][0] + b0f, 0.f) * w0
                    + fmaxf(acc[i][j][1] + b1f, 0.f) * w1;
                p1 += fmaxf(acc[i][j][2] + b0f, 0.f) * w0
                    + fmaxf(acc[i][j][3] + b1f, 0.f) * w1;
            }
            p0 += __shfl_xor_sync(0xffffffffu, p0, 1);
            p0 += __shfl_xor_sync(0xffffffffu, p0, 2);
            p1 += __shfl_xor_sync(0xffffffffu, p1, 1);
            p1 += __shfl_xor_sync(0xffffffffu, p1, 2);
            if ((lane & 3) == 0) {
                const int r0 = m0 + wm * 64 + i * 16 + (lane >> 2);
                const int r1 = r0 + 8;
                if (r0 < M) atomicAdd(&outLogit[r0], p0);
                if (r1 < M) atomicAdd(&outLogit[r1], p1);
            }
        }
    }
}

// ---------------- head init / sigmoid ----------------
__global__ void initout_kernel(float* __restrict__ out, const float* __restrict__ bo, int n) {
    int i = blockIdx.x * blockDim.x + threadIdx.x;
    if (i < n) out[i] = bo[0];
}

__global__ void sigmoid_kernel(float* __restrict__ out, int n) {
    int i = blockIdx.x * blockDim.x + threadIdx.x;
    if (i < n) out[i] = 1.0f / (1.0f + expf(-out[i]));
}

// ---------------- launch ----------------

extern "C" void kernel_launch(void* const* d_in, const int* in_sizes, int n_in,
                              void* d_out, int out_size) {
    const float* x  = (const float*)d_in[0];
    const int*   ei = (const int*)  d_in[1];
    const float* W1 = (const float*)d_in[2];
    const float* b1 = (const float*)d_in[3];
    const float* W2 = (const float*)d_in[4];
    const float* b2 = (const float*)d_in[5];
    const float* Wo = (const float*)d_in[6];
    const float* bo = (const float*)d_in[7];
    float* out = (float*)d_out;

    const int N = in_sizes[0] / FDIM;
    const int E = in_sizes[1] / 2;
    const int* src = ei;
    const int* dst = ei + E;

    float *inv;
    __half *xh, *ag1, *h1, *ag2, *wh;
    int *cnt, *off, *eid;
    cudaGetSymbolAddress((void**)&inv, g_inv);
    cudaGetSymbolAddress((void**)&xh,  g_xh);
    cudaGetSymbolAddress((void**)&ag1, g_ag1);
    cudaGetSymbolAddress((void**)&h1,  g_h1);
    cudaGetSymbolAddress((void**)&ag2, g_ag2);
    cudaGetSymbolAddress((void**)&wh,  g_wh);
    cudaGetSymbolAddress((void**)&cnt, g_cnt);
    cudaGetSymbolAddress((void**)&off, g_off);
    cudaGetSymbolAddress((void**)&eid, g_eid);

    const int T = 256;

    // ---- CSR build ----
    zeroi_kernel<<<(N + T - 1) / T, T>>>(cnt, N);
    count_kernel<<<(E + T - 1) / T, T>>>(dst, E, cnt);
    scan_kernel<<<1, 1024>>>(cnt, off, inv, N);
    zeroi_kernel<<<(N + T - 1) / T, T>>>(cnt, N);
    fill_kernel<<<(E + T - 1) / T, T>>>(src, dst, E, off, cnt, eid);

    // ---- layer 1 ----
    {
        int n4 = N * FDIM / 4;
        tohalf_kernel<<<(n4 + T - 1) / T, T>>>(x, xh, n4);
        int w4 = HDIM * 2 * FDIM / 4;
        tohalf_kernel<<<(w4 + T - 1) / T, T>>>(W1, wh, w4);
        gather_f16<16><<<(N + 15) / 16, 256>>>(xh, off, eid, inv, ag1, N);
        dim3 grid((N + 127) / 128, HDIM / 128);
        gemm_f16<0><<<grid, 256>>>(xh, ag1, wh, b1, h1, nullptr, nullptr, N, FDIM);
    }

    // ---- layer 2 (head fused) ----
    {
        int w4 = HDIM * 2 * HDIM / 4;
        tohalf_kernel<<<(w4 + T - 1) / T, T>>>(W2, wh, w4);
        gather_f16<64><<<(N + 3) / 4, 256>>>(h1, off, eid, inv, ag2, N);
        initout_kernel<<<(N + T - 1) / T, T>>>(out, bo, N);
        dim3 grid((N + 127) / 128, HDIM / 128);
        gemm_f16<1><<<grid, 256>>>(h1, ag2, wh, b2, nullptr, Wo, out, N, HDIM);
    }

    sigmoid_kernel<<<(N + T - 1) / T, T>>>(out, N);
}

// round 7
// speedup vs baseline: 5.6244x; 1.0500x over previous
#include <cuda_runtime.h>
#include <cuda_fp16.h>
#include <cstdint>
#include <math.h>

// ---------------------------------------------------------------------------
// GraphSAGE fraud detector — round 7.
//  * All-fp16 mma.sync GEMMs, CTA tile 128x256, warp tile 64x64.
//  * 3-stage cp.async smem pipeline (one barrier per K-chunk).
//  * CSR-gather aggregation; output head fused into GEMM2 epilogue.
// ---------------------------------------------------------------------------

#define MAXN 50048
#define MAXE 409600
#define HDIM 512
#define FDIM 128

#define STAGES   3
#define ASTAGE   8192     // 128 rows x 32 fp16
#define BSTAGE   16384    // 256 rows x 32 fp16
#define SMEM_TOT (STAGES * (ASTAGE + BSTAGE))   // 73728

__device__ __align__(16) float  g_inv[MAXN];
__device__ __align__(16) __half g_xh [(size_t)MAXN * FDIM];
__device__ __align__(16) __half g_ag1[(size_t)MAXN * FDIM];
__device__ __align__(16) __half g_h1 [(size_t)MAXN * HDIM];
__device__ __align__(16) __half g_ag2[(size_t)MAXN * HDIM];
__device__ __align__(16) __half g_wh [(size_t)HDIM * 1024];
__device__ int g_cnt[MAXN];
__device__ int g_off[MAXN + 1];
__device__ int g_eid[MAXE];

// ======================= helpers =============================

__device__ __forceinline__ uint32_t smem_u32(const void* p) {
    uint32_t a;
    asm("{ .reg .u64 t; cvta.to.shared.u64 t, %1; cvt.u32.u64 %0, t; }"
        : "=r"(a) : "l"(p));
    return a;
}

__device__ __forceinline__ void ldsm4(uint32_t* r, uint32_t addr) {
    asm volatile("ldmatrix.sync.aligned.m8n8.x4.shared.b16 {%0,%1,%2,%3}, [%4];"
                 : "=r"(r[0]), "=r"(r[1]), "=r"(r[2]), "=r"(r[3]) : "r"(addr));
}

__device__ __forceinline__ void mma16816(float* d, const uint32_t* a, const uint32_t* b) {
    asm volatile(
        "mma.sync.aligned.m16n8k16.row.col.f32.f16.f16.f32 "
        "{%0,%1,%2,%3}, {%4,%5,%6,%7}, {%8,%9}, {%0,%1,%2,%3};"
        : "+f"(d[0]), "+f"(d[1]), "+f"(d[2]), "+f"(d[3])
        : "r"(a[0]), "r"(a[1]), "r"(a[2]), "r"(a[3]), "r"(b[0]), "r"(b[1]));
}

__device__ __forceinline__ void cp16(uint32_t dst, const void* src, int src_sz) {
    asm volatile("cp.async.cg.shared.global [%0], [%1], 16, %2;"
                 :: "r"(dst), "l"(src), "r"(src_sz) : "memory");
}

#define CP_COMMIT() asm volatile("cp.async.commit_group;" ::: "memory")
#define CP_WAIT1()  asm volatile("cp.async.wait_group 1;" ::: "memory")

__device__ __forceinline__ uint32_t pack_h2(float a, float b) {
    __half2 h = __floats2half2_rn(a, b);
    return *(uint32_t*)&h;
}

// Tile addressing: logical rows x 32 fp16, packed 2 logical rows per 128B
// physical row, XOR-swizzled over 8 16B slots. Conflict-free ldmatrix.
__device__ __forceinline__ uint32_t taddr(int r, int c16) {
    return (uint32_t)((r >> 1) * 128 + ((((r & 1) * 4 + c16) ^ ((r >> 1) & 7)) << 4));
}

// ======================= CSR build =============================

__global__ void zeroi_kernel(int* __restrict__ p, int n) {
    int i = blockIdx.x * blockDim.x + threadIdx.x;
    if (i < n) p[i] = 0;
}

__global__ void count_kernel(const int* __restrict__ dst, int E, int* __restrict__ cnt) {
    int e = blockIdx.x * blockDim.x + threadIdx.x;
    if (e < E) atomicAdd(&cnt[dst[e]], 1);
}

__global__ void scan_kernel(const int* __restrict__ cnt, int* __restrict__ off,
                            float* __restrict__ inv, int n) {
    __shared__ int s[1024];
    const int t = threadIdx.x;
    const int chunk = (n + 1023) >> 10;
    const int start = t * chunk;
    const int end   = min(start + chunk, n);

    int sum = 0;
    for (int i = start; i < end; ++i) sum += cnt[i];
    s[t] = sum;
    __syncthreads();
#pragma unroll
    for (int o = 1; o < 1024; o <<= 1) {
        int v = (t >= o) ? s[t - o] : 0;
        __syncthreads();
        s[t] += v;
        __syncthreads();
    }
    int run = (t == 0) ? 0 : s[t - 1];
    for (int i = start; i < end; ++i) {
        off[i] = run;
        int c = cnt[i];
        inv[i] = 1.0f / fmaxf((float)c, 1.0f);
        run += c;
    }
    if (t == 0) off[n] = s[1023];
}

__global__ void fill_kernel(const int* __restrict__ src, const int* __restrict__ dst,
                            int E, const int* __restrict__ off,
                            int* __restrict__ pos, int* __restrict__ eid) {
    int e = blockIdx.x * blockDim.x + threadIdx.x;
    if (e < E) {
        int d = dst[e];
        int p = atomicAdd(&pos[d], 1);
        eid[off[d] + p] = src[e];
    }
}

// ---------------- fp32 -> fp16 convert (vectorized) ----------------
__global__ void tohalf_kernel(const float* __restrict__ src, __half* __restrict__ dstp,
                              int n4) {
    int i = blockIdx.x * blockDim.x + threadIdx.x;
    if (i < n4) {
        float4 v = ((const float4*)src)[i];
        uint2 o;
        o.x = pack_h2(v.x, v.y);
        o.y = pack_h2(v.z, v.w);
        ((uint2*)dstp)[i] = o;
    }
}

// ---------------- CSR gather (fp16): mean of incoming features -------------
template <int U>
__global__ void gather_f16(const __half* __restrict__ feat,
                           const int* __restrict__ off,
                           const int* __restrict__ eid,
                           const float* __restrict__ inv,
                           __half* __restrict__ outp, int N) {
    const int g = blockIdx.x * (256 / U) + threadIdx.x / U;
    const int c = threadIdx.x % U;
    if (g >= N) return;
    const int b  = off[g];
    const int e2 = off[g + 1];
    float acc[8];
#pragma unroll
    for (int q = 0; q < 8; ++q) acc[q] = 0.f;
    const uint4* base = (const uint4*)feat;
#pragma unroll 2
    for (int j = b; j < e2; ++j) {
        int s = __ldg(&eid[j]);
        uint4 u = __ldg(&base[(long long)s * U + c]);
        const __half2* h = (const __half2*)&u;
#pragma unroll
        for (int q = 0; q < 4; ++q) {
            float2 f = __half22float2(h[q]);
            acc[2 * q]     += f.x;
            acc[2 * q + 1] += f.y;
        }
    }
    const float sc = inv[g];
    uint4 o;
    o.x = pack_h2(acc[0] * sc, acc[1] * sc);
    o.y = pack_h2(acc[2] * sc, acc[3] * sc);
    o.z = pack_h2(acc[4] * sc, acc[5] * sc);
    o.w = pack_h2(acc[6] * sc, acc[7] * sc);
    ((uint4*)outp)[(long long)g * U + c] = o;
}

// =================== mma.sync fp16 concat-GEMM, multistage =================
// C[m, n] = relu( sum_k concat(A1[m,:], A2[m,:])[k] * W[n, k] + bias[n] )
// CTA 128(M) x 256(N); 8 warps, each 64x64; K chunks of 32; 3-stage cp.async.
// FUSED 0: epilogue bias+ReLU -> fp16 C.
// FUSED 1: epilogue head: atomicAdd(outLogit[m], sum_n relu(.)*Wo[n]).

template <int FUSED>
__global__ void __launch_bounds__(256, 1)
gemm_f16(const __half* __restrict__ A1, const __half* __restrict__ A2,
         const __half* __restrict__ W,
         const float* __restrict__ bias, __half* __restrict__ C,
         const float* __restrict__ Wo, float* __restrict__ outLogit,
         int M, int Kh) {
    extern __shared__ __align__(128) uint8_t dynsmem[];
    const uint32_t sbA = smem_u32(dynsmem);                 // 3 x 8KB
    const uint32_t sbB = sbA + STAGES * ASTAGE;             // 3 x 16KB

    const int tid  = threadIdx.x;
    const int wid  = tid >> 5;
    const int lane = tid & 31;
    const int wm   = wid & 1;        // 64-row band
    const int wn   = wid >> 1;       // 64-col band (0..3)
    const int K    = 2 * Kh;
    const int m0   = blockIdx.x * 128;
    const int n0   = blockIdx.y * 256;

    const int qrow = lane & 15;
    const int qsel = lane >> 4;

    float acc[4][8][4];
#pragma unroll
    for (int i = 0; i < 4; ++i)
#pragma unroll
        for (int j = 0; j < 8; ++j)
#pragma unroll
            for (int r = 0; r < 4; ++r) acc[i][j][r] = 0.0f;

    const int nch = K >> 5;

    // ---- async loader: chunk ch -> stage st ----
    auto issue_chunk = [&](int ch, int st) {
        const int k0 = ch << 5;
        const bool useA2 = (k0 >= Kh);
        const int koff = useA2 ? k0 - Kh : k0;
        const __half* Ab = useA2 ? A2 : A1;
        const uint32_t abase = sbA + st * ASTAGE;
        const uint32_t bbase = sbB + st * BSTAGE;
        // A: 512 16B units, 2 per thread
#pragma unroll
        for (int u0 = 0; u0 < 2; ++u0) {
            const int u = tid + u0 * 256;
            const int row = u >> 2, c16 = u & 3;
            const int m = m0 + row;
            const void* src = Ab + (long long)m * Kh + koff + c16 * 8;
            cp16(abase + taddr(row, c16), src, (m < M) ? 16 : 0);
        }
        // B: 1024 16B units, 4 per thread (n rows always valid: n0+row < 512)
#pragma unroll
        for (int u0 = 0; u0 < 4; ++u0) {
            const int u = tid + u0 * 256;
            const int row = u >> 2, c16 = u & 3;
            const void* src = W + (long long)(n0 + row) * K + k0 + c16 * 8;
            cp16(bbase + taddr(row, c16), src, 16);
        }
    };

    // prologue: stages 0, 1
    issue_chunk(0, 0); CP_COMMIT();
    issue_chunk(1, 1); CP_COMMIT();

    for (int ch = 0; ch < nch; ++ch) {
        CP_WAIT1();            // chunk ch resident
        __syncthreads();       // all warps past previous stage's compute
        {                      // refill the stage retired last iteration
            const int nxt = ch + STAGES - 1;
            if (nxt < nch) issue_chunk(nxt, nxt % STAGES);
            CP_COMMIT();       // always commit (possibly empty) — keeps count
        }

        const int st = ch % STAGES;
        const uint32_t aST = sbA + st * ASTAGE;
        const uint32_t bST = sbB + st * BSTAGE;

#pragma unroll
        for (int s = 0; s < 2; ++s) {
            const int cc = s * 2 + qsel;
            uint32_t ah[4][4], bh[4][4];
#pragma unroll
            for (int i = 0; i < 4; ++i)
                ldsm4(ah[i], aST + taddr(wm * 64 + i * 16 + qrow, cc));
#pragma unroll
            for (int p = 0; p < 4; ++p)
                ldsm4(bh[p], bST + taddr(wn * 64 + p * 16 + qrow, cc));
#pragma unroll
            for (int i = 0; i < 4; ++i) {
#pragma unroll
                for (int p = 0; p < 4; ++p) {
                    uint32_t f0[2] = { bh[p][0], bh[p][2] };
                    uint32_t f1[2] = { bh[p][1], bh[p][3] };
                    mma16816(acc[i][2 * p],     ah[i], f0);
                    mma16816(acc[i][2 * p + 1], ah[i], f1);
                }
            }
        }
    }
    __syncthreads();

    if (FUSED == 0) {
        // ---- epilogue: bias + ReLU -> fp16 C ----
#pragma unroll
        for (int j = 0; j < 8; ++j) {
            const int nb = n0 + wn * 64 + j * 8 + (lane & 3) * 2;
            const float b0f = bias[nb], b1f = bias[nb + 1];
#pragma unroll
            for (int i = 0; i < 4; ++i) {
                const int r0 = m0 + wm * 64 + i * 16 + (lane >> 2);
                if (r0 < M) {
                    *(uint32_t*)(C + (long long)r0 * HDIM + nb) =
                        pack_h2(fmaxf(acc[i][j][0] + b0f, 0.f),
                                fmaxf(acc[i][j][1] + b1f, 0.f));
                }
                const int r1 = r0 + 8;
                if (r1 < M) {
                    *(uint32_t*)(C + (long long)r1 * HDIM + nb) =
                        pack_h2(fmaxf(acc[i][j][2] + b0f, 0.f),
                                fmaxf(acc[i][j][3] + b1f, 0.f));
                }
            }
        }
    } else {
        // ---- epilogue: fused head — partial logits ----
#pragma unroll
        for (int i = 0; i < 4; ++i) {
            float p0 = 0.f, p1 = 0.f;
#pragma unroll
            for (int j = 0; j < 8; ++j) {
                const int nb = n0 + wn * 64 + j * 8 + (lane & 3) * 2;
                const float b0f = bias[nb],  b1f = bias[nb + 1];
                const float w0 = __ldg(&Wo[nb]), w1 = __ldg(&Wo[nb + 1]);
                p0 += fmaxf(acc[i][j][0] + b0f, 0.f) * w0
                    + fmaxf(acc[i][j][1] + b1f, 0.f) * w1;
                p1 += fmaxf(acc[i][j][2] + b0f, 0.f) * w0
                    + fmaxf(acc[i][j][3] + b1f, 0.f) * w1;
            }
            p0 += __shfl_xor_sync(0xffffffffu, p0, 1);
            p0 += __shfl_xor_sync(0xffffffffu, p0, 2);
            p1 += __shfl_xor_sync(0xffffffffu, p1, 1);
            p1 += __shfl_xor_sync(0xffffffffu, p1, 2);
            if ((lane & 3) == 0) {
                const int r0 = m0 + wm * 64 + i * 16 + (lane >> 2);
                const int r1 = r0 + 8;
                if (r0 < M) atomicAdd(&outLogit[r0], p0);
                if (r1 < M) atomicAdd(&outLogit[r1], p1);
            }
        }
    }
}

// ---------------- head init / sigmoid ----------------
__global__ void initout_kernel(float* __restrict__ out, const float* __restrict__ bo, int n) {
    int i = blockIdx.x * blockDim.x + threadIdx.x;
    if (i < n) out[i] = bo[0];
}

__global__ void sigmoid_kernel(float* __restrict__ out, int n) {
    int i = blockIdx.x * blockDim.x + threadIdx.x;
    if (i < n) out[i] = 1.0f / (1.0f + expf(-out[i]));
}

// ---------------- launch ----------------

extern "C" void kernel_launch(void* const* d_in, const int* in_sizes, int n_in,
                              void* d_out, int out_size) {
    const float* x  = (const float*)d_in[0];
    const int*   ei = (const int*)  d_in[1];
    const float* W1 = (const float*)d_in[2];
    const float* b1 = (const float*)d_in[3];
    const float* W2 = (const float*)d_in[4];
    const float* b2 = (const float*)d_in[5];
    const float* Wo = (const float*)d_in[6];
    const float* bo = (const float*)d_in[7];
    float* out = (float*)d_out;

    const int N = in_sizes[0] / FDIM;
    const int E = in_sizes[1] / 2;
    const int* src = ei;
    const int* dst = ei + E;

    float *inv;
    __half *xh, *ag1, *h1, *ag2, *wh;
    int *cnt, *off, *eid;
    cudaGetSymbolAddress((void**)&inv, g_inv);
    cudaGetSymbolAddress((void**)&xh,  g_xh);
    cudaGetSymbolAddress((void**)&ag1, g_ag1);
    cudaGetSymbolAddress((void**)&h1,  g_h1);
    cudaGetSymbolAddress((void**)&ag2, g_ag2);
    cudaGetSymbolAddress((void**)&wh,  g_wh);
    cudaGetSymbolAddress((void**)&cnt, g_cnt);
    cudaGetSymbolAddress((void**)&off, g_off);
    cudaGetSymbolAddress((void**)&eid, g_eid);

    cudaFuncSetAttribute(gemm_f16<0>, cudaFuncAttributeMaxDynamicSharedMemorySize, SMEM_TOT);
    cudaFuncSetAttribute(gemm_f16<1>, cudaFuncAttributeMaxDynamicSharedMemorySize, SMEM_TOT);

    const int T = 256;

    // ---- CSR build ----
    zeroi_kernel<<<(N + T - 1) / T, T>>>(cnt, N);
    count_kernel<<<(E + T - 1) / T, T>>>(dst, E, cnt);
    scan_kernel<<<1, 1024>>>(cnt, off, inv, N);
    zeroi_kernel<<<(N + T - 1) / T, T>>>(cnt, N);
    fill_kernel<<<(E + T - 1) / T, T>>>(src, dst, E, off, cnt, eid);

    // ---- layer 1 ----
    {
        int n4 = N * FDIM / 4;
        tohalf_kernel<<<(n4 + T - 1) / T, T>>>(x, xh, n4);
        int w4 = HDIM * 2 * FDIM / 4;
        tohalf_kernel<<<(w4 + T - 1) / T, T>>>(W1, wh, w4);
        gather_f16<16><<<(N + 15) / 16, 256>>>(xh, off, eid, inv, ag1, N);
        dim3 grid((N + 127) / 128, HDIM / 256);
        gemm_f16<0><<<grid, 256, SMEM_TOT>>>(xh, ag1, wh, b1, h1, nullptr, nullptr, N, FDIM);
    }

    // ---- layer 2 (head fused) ----
    {
        int w4 = HDIM * 2 * HDIM / 4;
        tohalf_kernel<<<(w4 + T - 1) / T, T>>>(W2, wh, w4);
        gather_f16<64><<<(N + 3) / 4, 256>>>(h1, off, eid, inv, ag2, N);
        initout_kernel<<<(N + T - 1) / T, T>>>(out, bo, N);
        dim3 grid((N + 127) / 128, HDIM / 256);
        gemm_f16<1><<<grid, 256, SMEM_TOT>>>(h1, ag2, wh, b2, nullptr, Wo, out, N, HDIM);
    }

    sigmoid_kernel<<<(N + T - 1) / T, T>>>(out, N);
}